// round 1
// baseline (speedup 1.0000x reference)
#include <cuda_runtime.h>
#include <math.h>
#include <stdint.h>

// Problem dims
#define BB 2
#define SS 2048
#define NTOK 4096        // BB*SS
#define HH 768
#define NHEAD 12
#define HDIM 64
#define NLAYER 6
#define IFF 3072
#define MFEAT 256
#define EPSF 1e-6f
#define DN 0.3535533905932738f   // 1/sqrt(sqrt(64))
#define RATIO 0.0625f            // 1/sqrt(256)

// ---------------- scratch (device globals; allocation-free) ----------------
__device__ float g_x[NTOK * HH];
__device__ float g_a[NTOK * HH];
__device__ float g_q[NTOK * HH];
__device__ float g_k[NTOK * HH];
__device__ float g_v[NTOK * HH];
__device__ float g_qp[(long)NTOK * NHEAD * MFEAT];
__device__ float g_kp[(long)NTOK * NHEAD * MFEAT];
__device__ float g_kd[NTOK * NHEAD];
__device__ float g_kmax[BB * NHEAD];
__device__ float g_kvb[BB * NHEAD * MFEAT * HDIM];
__device__ float g_ksum[BB * NHEAD * MFEAT];
__device__ float g_num[NTOK * HH];
__device__ float g_den[NTOK * NHEAD];
__device__ float g_attout[NTOK * HH];
__device__ float g_inter[(long)NTOK * IFF];
__device__ float g_ffout[NTOK * HH];

// ---------------- helpers ----------------
__device__ __forceinline__ float warp_sum(float v) {
#pragma unroll
    for (int o = 16; o > 0; o >>= 1) v += __shfl_xor_sync(0xffffffffu, v, o);
    return v;
}
__device__ __forceinline__ float warp_max(float v) {
#pragma unroll
    for (int o = 16; o > 0; o >>= 1) v = fmaxf(v, __shfl_xor_sync(0xffffffffu, v, o));
    return v;
}
__device__ __forceinline__ void atomicMaxFloat(float* addr, float val) {
    if (val >= 0.f) atomicMax((int*)addr, __float_as_int(val));
    else            atomicMin((unsigned int*)addr, __float_as_uint(val));
}
__device__ __forceinline__ float gelu_tanh(float v) {
    float x3 = v * v * v;
    return 0.5f * v * (1.f + tanhf(0.7978845608028654f * (v + 0.044715f * x3)));
}

// ---------------- generic tiled SGEMM ----------------
// C[r,c] (+= base offsets by blockIdx.z) = alpha * sum_k A(r,k)*B(k,c)  [+bias[c]] [gelu]
// TA=0: A(r,k)=A[r*lda+k]; TA=1: A(r,k)=A[k*lda+r]
// TB=0: B(k,c)=B[k*ldb+c]; TB=1: B(k,c)=B[c*ldb+k]
// batch offsets: off = (z/zdiv)*s1 + (z%zdiv)*s2 for each of A,B,C
template <int TA, int TB, int EPI>
__global__ void __launch_bounds__(256) sgemm_kernel(
    const float* __restrict__ A, int lda,
    const float* __restrict__ B, int ldb,
    const float* __restrict__ bias,
    float* __restrict__ C, int ldc,
    int K, float alpha,
    int zdiv, long sA1, long sA2, long sB1, long sB2, long sC1, long sC2)
{
    int z = blockIdx.z;
    int z1 = z / zdiv, z2 = z % zdiv;
    A += z1 * sA1 + z2 * sA2;
    B += z1 * sB1 + z2 * sB2;
    C += z1 * sC1 + z2 * sC2;

    __shared__ float As[16][65];
    __shared__ float Bs[16][65];

    const int tid = threadIdx.x;
    const int tx = tid & 15;         // col group
    const int ty = tid >> 4;         // row group
    const int row0 = blockIdx.y * 64;
    const int col0 = blockIdx.x * 64;

    float acc[4][4] = {};

    for (int k0 = 0; k0 < K; k0 += 16) {
        // load A tile (64 rows x 16 k)
#pragma unroll
        for (int i = 0; i < 4; i++) {
            int e = tid + i * 256;
            if (TA == 0) {
                int r = e >> 4, c = e & 15;
                As[c][r] = A[(long)(row0 + r) * lda + k0 + c];
            } else {
                int r = e & 63, c = e >> 6;
                As[c][r] = A[(long)(k0 + c) * lda + row0 + r];
            }
        }
        // load B tile (16 k x 64 cols)
#pragma unroll
        for (int i = 0; i < 4; i++) {
            int e = tid + i * 256;
            if (TB == 0) {
                int r = e >> 6, c = e & 63;
                Bs[r][c] = B[(long)(k0 + r) * ldb + col0 + c];
            } else {
                int r = e & 15, c = e >> 4;
                Bs[r][c] = B[(long)(col0 + c) * ldb + k0 + r];
            }
        }
        __syncthreads();
#pragma unroll
        for (int kk = 0; kk < 16; kk++) {
            float av[4], bv[4];
#pragma unroll
            for (int i = 0; i < 4; i++) av[i] = As[kk][ty * 4 + i];
#pragma unroll
            for (int j = 0; j < 4; j++) bv[j] = Bs[kk][tx * 4 + j];
#pragma unroll
            for (int i = 0; i < 4; i++)
#pragma unroll
                for (int j = 0; j < 4; j++)
                    acc[i][j] = fmaf(av[i], bv[j], acc[i][j]);
        }
        __syncthreads();
    }

#pragma unroll
    for (int i = 0; i < 4; i++) {
        int row = row0 + ty * 4 + i;
#pragma unroll
        for (int j = 0; j < 4; j++) {
            int col = col0 + tx * 4 + j;
            float v = acc[i][j] * alpha;
            if (EPI >= 1) v += bias[col];
            if (EPI == 2) v = gelu_tanh(v);
            C[(long)row * ldc + col] = v;
        }
    }
}

// ---------------- embedding + layernorm ----------------
__global__ void embed_ln_kernel(const int* __restrict__ ids,
                                const int* __restrict__ tts,
                                const int* __restrict__ poss,
                                const float* __restrict__ we,
                                const float* __restrict__ pe,
                                const float* __restrict__ te,
                                const float* __restrict__ g,
                                const float* __restrict__ b,
                                float* __restrict__ out)
{
    int t = blockIdx.x;
    int id = ids[t], tk = tts[t], ps = poss[t];
    __shared__ float buf[HH];
    __shared__ float red[16];
    float s = 0.f, sq = 0.f;
    for (int h = threadIdx.x; h < HH; h += 256) {
        float v = we[(long)id * HH + h] + pe[(long)ps * HH + h] + te[(long)tk * HH + h];
        buf[h] = v; s += v; sq += v * v;
    }
    s = warp_sum(s); sq = warp_sum(sq);
    if ((threadIdx.x & 31) == 0) { red[threadIdx.x >> 5] = s; red[8 + (threadIdx.x >> 5)] = sq; }
    __syncthreads();
    float ts = 0.f, tq = 0.f;
#pragma unroll
    for (int i = 0; i < 8; i++) { ts += red[i]; tq += red[8 + i]; }
    float mu = ts * (1.f / HH);
    float var = tq * (1.f / HH) - mu * mu;
    float inv = rsqrtf(var + EPSF);
    for (int h = threadIdx.x; h < HH; h += 256)
        out[(long)t * HH + h] = (buf[h] - mu) * inv * g[h] + b[h];
}

// ---------------- residual + layernorm: out = LN(in1 + in2) ----------------
__global__ void ln_res_kernel(const float* __restrict__ in1,
                              const float* __restrict__ in2,
                              const float* __restrict__ g,
                              const float* __restrict__ b,
                              float* __restrict__ out)
{
    int t = blockIdx.x;
    __shared__ float buf[HH];
    __shared__ float red[16];
    float s = 0.f, sq = 0.f;
    for (int h = threadIdx.x; h < HH; h += 256) {
        float v = in1[(long)t * HH + h] + in2[(long)t * HH + h];
        buf[h] = v; s += v; sq += v * v;
    }
    s = warp_sum(s); sq = warp_sum(sq);
    if ((threadIdx.x & 31) == 0) { red[threadIdx.x >> 5] = s; red[8 + (threadIdx.x >> 5)] = sq; }
    __syncthreads();
    float ts = 0.f, tq = 0.f;
#pragma unroll
    for (int i = 0; i < 8; i++) { ts += red[i]; tq += red[8 + i]; }
    float mu = ts * (1.f / HH);
    float var = tq * (1.f / HH) - mu * mu;
    float inv = rsqrtf(var + EPSF);
    for (int h = threadIdx.x; h < HH; h += 256)
        out[(long)t * HH + h] = (buf[h] - mu) * inv * g[h] + b[h];
}

// ---------------- FAVOR+ epilogues ----------------
// q': per-row (b,s,n): ratio*(exp(qp - qd - rowmax) + eps). One warp per row.
__global__ void q_epi_kernel(float* __restrict__ qp, const float* __restrict__ q)
{
    int row = blockIdx.x * 8 + (threadIdx.x >> 5);
    int lane = threadIdx.x & 31;
    const float* qr = q + (long)row * HDIM;
    float s = 0.f;
#pragma unroll
    for (int i = 0; i < 2; i++) { float v = qr[lane + i * 32] * DN; s += v * v; }
    s = warp_sum(s);
    float qd = 0.5f * s;
    float* qpr = qp + (long)row * MFEAT;
    float vals[8]; float mx = -INFINITY;
#pragma unroll
    for (int i = 0; i < 8; i++) { vals[i] = qpr[lane + i * 32]; mx = fmaxf(mx, vals[i]); }
    mx = warp_max(mx);
#pragma unroll
    for (int i = 0; i < 8; i++)
        qpr[lane + i * 32] = RATIO * (expf(vals[i] - qd - mx) + EPSF);
}

__global__ void kmax_init_kernel(float* __restrict__ kmax)
{
    if (threadIdx.x < BB * NHEAD) kmax[threadIdx.x] = -INFINITY;
}

// pass1: kd per row, global max per (b,n) via atomicMax
__global__ void k_epi1_kernel(const float* __restrict__ kp, const float* __restrict__ k,
                              float* __restrict__ kd, float* __restrict__ kmax)
{
    int row = blockIdx.x * 8 + (threadIdx.x >> 5);
    int lane = threadIdx.x & 31;
    const float* kr = k + (long)row * HDIM;
    float s = 0.f;
#pragma unroll
    for (int i = 0; i < 2; i++) { float v = kr[lane + i * 32] * DN; s += v * v; }
    s = warp_sum(s);
    const float* kpr = kp + (long)row * MFEAT;
    float mx = -INFINITY;
#pragma unroll
    for (int i = 0; i < 8; i++) mx = fmaxf(mx, kpr[lane + i * 32]);
    mx = warp_max(mx);
    if (lane == 0) {
        kd[row] = 0.5f * s;
        int n = row % NHEAD;
        int t = row / NHEAD;
        int b = t >> 11;  // /2048
        atomicMaxFloat(&kmax[b * NHEAD + n], mx);
    }
}

// pass2: k' = ratio*(exp(kp - kd - kmax)+eps) * mask
__global__ void k_epi2_kernel(float* __restrict__ kp, const float* __restrict__ kd,
                              const float* __restrict__ kmax, const int* __restrict__ am)
{
    long idx = (long)blockIdx.x * 256 + threadIdx.x;
    if (idx >= (long)NTOK * NHEAD * MFEAT) return;
    int row = (int)(idx >> 8);
    int n = row % NHEAD;
    int t = row / NHEAD;
    int b = t >> 11;
    float v = kp[idx];
    float r = RATIO * (expf(v - kd[row] - kmax[b * NHEAD + n]) + EPSF);
    kp[idx] = r * (float)am[t];
}

// ksum[b,n,m] = sum_s k'[b,s,n,m]
__global__ void ksum_kernel(const float* __restrict__ kp, float* __restrict__ ksum)
{
    int bn = blockIdx.x;
    int b = bn / NHEAD, n = bn % NHEAD;
    int m = threadIdx.x;
    const float* base = kp + ((long)(b * SS) * NHEAD + n) * MFEAT + m;
    float s = 0.f;
    for (int ss = 0; ss < SS; ss++) s += base[(long)ss * NHEAD * MFEAT];
    ksum[bn * MFEAT + m] = s;
}

// den[row] = dot(q'[row], ksum[b,n])
__global__ void den_kernel(const float* __restrict__ qp, const float* __restrict__ ksum,
                           float* __restrict__ den)
{
    int row = blockIdx.x * 8 + (threadIdx.x >> 5);
    int lane = threadIdx.x & 31;
    int n = row % NHEAD;
    int t = row / NHEAD;
    int b = t >> 11;
    const float* qpr = qp + (long)row * MFEAT;
    const float* ks = ksum + (b * NHEAD + n) * MFEAT;
    float s = 0.f;
#pragma unroll
    for (int i = 0; i < 8; i++) { int m = lane + i * 32; s += qpr[m] * ks[m]; }
    s = warp_sum(s);
    if (lane == 0) den[row] = s;
}

__global__ void div_kernel(float* __restrict__ num, const float* __restrict__ den)
{
    long idx = (long)blockIdx.x * 256 + threadIdx.x;
    if (idx >= (long)NTOK * HH) return;
    num[idx] /= den[idx >> 6];
}

// ---------------- host launch ----------------
extern "C" void kernel_launch(void* const* d_in, const int* in_sizes, int n_in,
                              void* d_out, int out_size)
{
    const int* ids  = (const int*)d_in[0];
    const int* tts  = (const int*)d_in[1];
    const int* poss = (const int*)d_in[2];
    const int* am   = (const int*)d_in[3];
    const float* we   = (const float*)d_in[4];
    const float* pe   = (const float*)d_in[5];
    const float* te   = (const float*)d_in[6];
    const float* elg  = (const float*)d_in[7];
    const float* elb  = (const float*)d_in[8];
    const float* wq   = (const float*)d_in[9];
    const float* bq   = (const float*)d_in[10];
    const float* wk   = (const float*)d_in[11];
    const float* bk   = (const float*)d_in[12];
    const float* wv   = (const float*)d_in[13];
    const float* bv   = (const float*)d_in[14];
    const float* wo   = (const float*)d_in[15];
    const float* bo   = (const float*)d_in[16];
    const float* ln1g = (const float*)d_in[17];
    const float* ln1b = (const float*)d_in[18];
    const float* wi   = (const float*)d_in[19];
    const float* bi   = (const float*)d_in[20];
    const float* wo2  = (const float*)d_in[21];
    const float* bo2  = (const float*)d_in[22];
    const float* ln2g = (const float*)d_in[23];
    const float* ln2b = (const float*)d_in[24];
    const float* proj = (const float*)d_in[25];

    float *x, *a, *q, *k, *v, *qp, *kp, *kd, *kmax, *kvb, *ksum, *num, *den, *attout, *inter, *ffout;
    cudaGetSymbolAddress((void**)&x, g_x);
    cudaGetSymbolAddress((void**)&a, g_a);
    cudaGetSymbolAddress((void**)&q, g_q);
    cudaGetSymbolAddress((void**)&k, g_k);
    cudaGetSymbolAddress((void**)&v, g_v);
    cudaGetSymbolAddress((void**)&qp, g_qp);
    cudaGetSymbolAddress((void**)&kp, g_kp);
    cudaGetSymbolAddress((void**)&kd, g_kd);
    cudaGetSymbolAddress((void**)&kmax, g_kmax);
    cudaGetSymbolAddress((void**)&kvb, g_kvb);
    cudaGetSymbolAddress((void**)&ksum, g_ksum);
    cudaGetSymbolAddress((void**)&num, g_num);
    cudaGetSymbolAddress((void**)&den, g_den);
    cudaGetSymbolAddress((void**)&attout, g_attout);
    cudaGetSymbolAddress((void**)&inter, g_inter);
    cudaGetSymbolAddress((void**)&ffout, g_ffout);

    // embeddings + LN
    embed_ln_kernel<<<NTOK, 256>>>(ids, tts, poss, we, pe, te, elg, elb, x);

    const long HW = (long)HH * HH;          // 589824
    for (int l = 0; l < NLAYER; l++) {
        // ---- QKV projections ----
        sgemm_kernel<0, 0, 1><<<dim3(HH / 64, NTOK / 64, 1), 256>>>(
            x, HH, wq + l * HW, HH, bq + l * HH, q, HH, HH, 1.f,
            1, 0, 0, 0, 0, 0, 0);
        sgemm_kernel<0, 0, 1><<<dim3(HH / 64, NTOK / 64, 1), 256>>>(
            x, HH, wk + l * HW, HH, bk + l * HH, k, HH, HH, 1.f,
            1, 0, 0, 0, 0, 0, 0);
        sgemm_kernel<0, 0, 1><<<dim3(HH / 64, NTOK / 64, 1), 256>>>(
            x, HH, wv + l * HW, HH, bv + l * HH, v, HH, HH, 1.f,
            1, 0, 0, 0, 0, 0, 0);

        // ---- feature maps: qp = dn * q @ proj^T, kp likewise ----
        sgemm_kernel<0, 1, 0><<<dim3(MFEAT / 64, (NTOK * NHEAD) / 64, 1), 256>>>(
            q, HDIM, proj + (long)l * MFEAT * HDIM, HDIM, nullptr,
            qp, MFEAT, HDIM, DN, 1, 0, 0, 0, 0, 0, 0);
        sgemm_kernel<0, 1, 0><<<dim3(MFEAT / 64, (NTOK * NHEAD) / 64, 1), 256>>>(
            k, HDIM, proj + (long)l * MFEAT * HDIM, HDIM, nullptr,
            kp, MFEAT, HDIM, DN, 1, 0, 0, 0, 0, 0, 0);

        // ---- FAVOR epilogues ----
        q_epi_kernel<<<(NTOK * NHEAD) / 8, 256>>>(qp, q);
        kmax_init_kernel<<<1, 32>>>(kmax);
        k_epi1_kernel<<<(NTOK * NHEAD) / 8, 256>>>(kp, k, kd, kmax);
        {
            long total = (long)NTOK * NHEAD * MFEAT;
            int blocks = (int)((total + 255) / 256);
            k_epi2_kernel<<<blocks, 256>>>(kp, kd, kmax, am);
        }

        // ---- kv[b,n] = k'^T v  (256x64, K=2048), batched over 24 (b,n) ----
        sgemm_kernel<1, 0, 0><<<dim3(1, MFEAT / 64, BB * NHEAD), 256>>>(
            kp, NHEAD * MFEAT, v, HH, nullptr, kvb, HDIM, SS, 1.f,
            NHEAD,
            (long)SS * NHEAD * MFEAT, MFEAT,            // A offsets (b, n)
            (long)SS * HH, HDIM,                        // B offsets
            (long)NHEAD * MFEAT * HDIM, (long)MFEAT * HDIM);  // C offsets

        ksum_kernel<<<BB * NHEAD, MFEAT>>>(kp, ksum);

        // ---- num[b,n] = q' @ kv  (2048x64, K=256), batched over 24 ----
        sgemm_kernel<0, 0, 0><<<dim3(1, SS / 64, BB * NHEAD), 256>>>(
            qp, NHEAD * MFEAT, kvb, HDIM, nullptr, num, HH, MFEAT, 1.f,
            NHEAD,
            (long)SS * NHEAD * MFEAT, MFEAT,
            (long)NHEAD * MFEAT * HDIM, (long)MFEAT * HDIM,
            (long)SS * HH, HDIM);

        den_kernel<<<(NTOK * NHEAD) / 8, 256>>>(qp, ksum, den);
        {
            long total = (long)NTOK * HH;
            int blocks = (int)((total + 255) / 256);
            div_kernel<<<blocks, 256>>>(num, den);
        }

        // ---- output projection + residual LN ----
        sgemm_kernel<0, 0, 1><<<dim3(HH / 64, NTOK / 64, 1), 256>>>(
            num, HH, wo + l * HW, HH, bo + l * HH, attout, HH, HH, 1.f,
            1, 0, 0, 0, 0, 0, 0);
        ln_res_kernel<<<NTOK, 256>>>(attout, x, ln1g + l * HH, ln1b + l * HH, a);

        // ---- FFN ----
        sgemm_kernel<0, 0, 2><<<dim3(IFF / 64, NTOK / 64, 1), 256>>>(
            a, HH, wi + (long)l * HH * IFF, IFF, bi + l * IFF, inter, IFF, HH, 1.f,
            1, 0, 0, 0, 0, 0, 0);
        sgemm_kernel<0, 0, 1><<<dim3(HH / 64, NTOK / 64, 1), 256>>>(
            inter, IFF, wo2 + (long)l * IFF * HH, HH, bo2 + l * HH, ffout, HH, IFF, 1.f,
            1, 0, 0, 0, 0, 0, 0);

        float* outp = (l == NLAYER - 1) ? (float*)d_out : x;
        ln_res_kernel<<<NTOK, 256>>>(ffout, a, ln2g + l * HH, ln2b + l * HH, outp);
    }
}

// round 2
// speedup vs baseline: 1.3014x; 1.3014x over previous
#include <cuda_runtime.h>
#include <math.h>
#include <stdint.h>

// Problem dims
#define BB 2
#define SS 2048
#define NTOK 4096        // BB*SS
#define HH 768
#define NHEAD 12
#define HDIM 64
#define NLAYER 6
#define IFF 3072
#define MFEAT 256
#define EPSF 1e-6f
#define DN 0.3535533905932738f   // 1/sqrt(sqrt(64))
#define RATIO 0.0625f            // 1/sqrt(256)
#define KVSPLIT 8
#define KVSLICE (BB * NHEAD * MFEAT * HDIM)   // 393216

// ---------------- scratch (device globals; allocation-free) ----------------
__device__ float g_x[NTOK * HH];
__device__ float g_a[NTOK * HH];
__device__ float g_q[NTOK * HH];
__device__ float g_k[NTOK * HH];
__device__ float g_v[NTOK * HH];
__device__ float g_qp[(long)NTOK * NHEAD * MFEAT];
__device__ float g_kp[(long)NTOK * NHEAD * MFEAT];
__device__ float g_kd[NTOK * NHEAD];
__device__ float g_kmax[BB * NHEAD];
__device__ float g_kvb[KVSLICE];
__device__ float g_kvpart[KVSPLIT * KVSLICE];
__device__ float g_ksum[BB * NHEAD * MFEAT];
__device__ float g_kspart[BB * NHEAD * 16 * MFEAT];
__device__ float g_num[NTOK * HH];
__device__ float g_den[NTOK * NHEAD];
__device__ float g_attout[NTOK * HH];
__device__ float g_inter[(long)NTOK * IFF];
__device__ float g_ffout[NTOK * HH];

// ---------------- helpers ----------------
__device__ __forceinline__ float warp_sum(float v) {
#pragma unroll
    for (int o = 16; o > 0; o >>= 1) v += __shfl_xor_sync(0xffffffffu, v, o);
    return v;
}
__device__ __forceinline__ float warp_max(float v) {
#pragma unroll
    for (int o = 16; o > 0; o >>= 1) v = fmaxf(v, __shfl_xor_sync(0xffffffffu, v, o));
    return v;
}
__device__ __forceinline__ void atomicMaxFloat(float* addr, float val) {
    if (val >= 0.f) atomicMax((int*)addr, __float_as_int(val));
    else            atomicMin((unsigned int*)addr, __float_as_uint(val));
}
__device__ __forceinline__ float gelu_tanh(float v) {
    float x3 = v * v * v;
    return 0.5f * v * (1.f + tanhf(0.7978845608028654f * (v + 0.044715f * x3)));
}

// ================= big-tile SGEMM: 128x128 tile, BK=16, 8x8 microtile ======
// C[r,c] = epi(alpha * sum_k A(r,k)*B(k,c))
// A row-major [M,K] (TA=0 always). TB=0: B[k*ldb+c]; TB=1: B[c*ldb+k].
// EPI: 0 none, 1 +bias, 2 +bias+gelu. M%128==0, N%128==0, K%16==0 required.
template <int TB, int EPI>
__global__ void __launch_bounds__(256) sgemm128_kernel(
    const float* __restrict__ A, int lda,
    const float* __restrict__ B, int ldb,
    const float* __restrict__ bias,
    float* __restrict__ C, int ldc,
    int K, float alpha)
{
    __shared__ float As[16][128];
    __shared__ float Bs[16][128];

    const int tid = threadIdx.x;
    const int tx = tid & 15;
    const int ty = tid >> 4;
    const int row0 = blockIdx.y * 128;
    const int col0 = blockIdx.x * 128;

    const int lr = tid >> 2;          // 0..63
    const int lc = (tid & 3) * 4;     // 0,4,8,12
    const int brw = tid >> 5;         // 0..7
    const int bcl = (tid & 31) * 4;   // 0..124

    const float* Abase0 = A + (long)(row0 + lr) * lda + lc;
    const float* Abase1 = Abase0 + 64l * lda;
    const float* Bbase0;
    const float* Bbase1;
    if (TB == 0) {
        Bbase0 = B + (long)brw * ldb + col0 + bcl;
        Bbase1 = B + (long)(brw + 8) * ldb + col0 + bcl;
    } else {
        Bbase0 = B + (long)(col0 + lr) * ldb + lc;
        Bbase1 = B + (long)(col0 + lr + 64) * ldb + lc;
    }

    float4 pa0 = *(const float4*)(Abase0);
    float4 pa1 = *(const float4*)(Abase1);
    float4 pb0 = *(const float4*)(Bbase0);
    float4 pb1 = *(const float4*)(Bbase1);

    // store tile 0
    As[lc + 0][lr] = pa0.x; As[lc + 1][lr] = pa0.y; As[lc + 2][lr] = pa0.z; As[lc + 3][lr] = pa0.w;
    As[lc + 0][lr + 64] = pa1.x; As[lc + 1][lr + 64] = pa1.y; As[lc + 2][lr + 64] = pa1.z; As[lc + 3][lr + 64] = pa1.w;
    if (TB == 0) {
        *(float4*)&Bs[brw][bcl] = pb0;
        *(float4*)&Bs[brw + 8][bcl] = pb1;
    } else {
        Bs[lc + 0][lr] = pb0.x; Bs[lc + 1][lr] = pb0.y; Bs[lc + 2][lr] = pb0.z; Bs[lc + 3][lr] = pb0.w;
        Bs[lc + 0][lr + 64] = pb1.x; Bs[lc + 1][lr + 64] = pb1.y; Bs[lc + 2][lr + 64] = pb1.z; Bs[lc + 3][lr + 64] = pb1.w;
    }

    float acc[8][8] = {};

    for (int k0 = 0; k0 < K; k0 += 16) {
        __syncthreads();
        const bool notlast = (k0 + 16) < K;
        if (notlast) {
            pa0 = *(const float4*)(Abase0 + k0 + 16);
            pa1 = *(const float4*)(Abase1 + k0 + 16);
            if (TB == 0) {
                pb0 = *(const float4*)(Bbase0 + (long)(k0 + 16) * ldb);
                pb1 = *(const float4*)(Bbase1 + (long)(k0 + 16) * ldb);
            } else {
                pb0 = *(const float4*)(Bbase0 + k0 + 16);
                pb1 = *(const float4*)(Bbase1 + k0 + 16);
            }
        }
#pragma unroll
        for (int kk = 0; kk < 16; kk++) {
            float4 a0 = *(const float4*)&As[kk][ty * 4];
            float4 a1 = *(const float4*)&As[kk][ty * 4 + 64];
            float4 b0 = *(const float4*)&Bs[kk][tx * 4];
            float4 b1 = *(const float4*)&Bs[kk][tx * 4 + 64];
            float av[8] = {a0.x, a0.y, a0.z, a0.w, a1.x, a1.y, a1.z, a1.w};
            float bv[8] = {b0.x, b0.y, b0.z, b0.w, b1.x, b1.y, b1.z, b1.w};
#pragma unroll
            for (int i = 0; i < 8; i++)
#pragma unroll
                for (int j = 0; j < 8; j++)
                    acc[i][j] = fmaf(av[i], bv[j], acc[i][j]);
        }
        if (notlast) {
            __syncthreads();
            As[lc + 0][lr] = pa0.x; As[lc + 1][lr] = pa0.y; As[lc + 2][lr] = pa0.z; As[lc + 3][lr] = pa0.w;
            As[lc + 0][lr + 64] = pa1.x; As[lc + 1][lr + 64] = pa1.y; As[lc + 2][lr + 64] = pa1.z; As[lc + 3][lr + 64] = pa1.w;
            if (TB == 0) {
                *(float4*)&Bs[brw][bcl] = pb0;
                *(float4*)&Bs[brw + 8][bcl] = pb1;
            } else {
                Bs[lc + 0][lr] = pb0.x; Bs[lc + 1][lr] = pb0.y; Bs[lc + 2][lr] = pb0.z; Bs[lc + 3][lr] = pb0.w;
                Bs[lc + 0][lr + 64] = pb1.x; Bs[lc + 1][lr + 64] = pb1.y; Bs[lc + 2][lr + 64] = pb1.z; Bs[lc + 3][lr + 64] = pb1.w;
            }
        }
    }

#pragma unroll
    for (int hi = 0; hi < 2; hi++) {
#pragma unroll
        for (int i = 0; i < 4; i++) {
            int row = row0 + hi * 64 + ty * 4 + i;
#pragma unroll
            for (int hj = 0; hj < 2; hj++) {
                int col = col0 + hj * 64 + tx * 4;
                float4 o;
                o.x = acc[hi * 4 + i][hj * 4 + 0] * alpha;
                o.y = acc[hi * 4 + i][hj * 4 + 1] * alpha;
                o.z = acc[hi * 4 + i][hj * 4 + 2] * alpha;
                o.w = acc[hi * 4 + i][hj * 4 + 3] * alpha;
                if (EPI >= 1) {
                    o.x += bias[col + 0]; o.y += bias[col + 1];
                    o.z += bias[col + 2]; o.w += bias[col + 3];
                }
                if (EPI == 2) {
                    o.x = gelu_tanh(o.x); o.y = gelu_tanh(o.y);
                    o.z = gelu_tanh(o.z); o.w = gelu_tanh(o.w);
                }
                *(float4*)&C[(long)row * ldc + col] = o;
            }
        }
    }
}

// ================= generic 64x64 tiled SGEMM (batched, optional K-split) ===
// z -> (zc = z % kz : K-chunk, rest -> z1 = rest/zdiv, z2 = rest%zdiv)
template <int TA, int TB, int EPI>
__global__ void __launch_bounds__(256) sgemm_kernel(
    const float* __restrict__ A, int lda,
    const float* __restrict__ B, int ldb,
    const float* __restrict__ bias,
    float* __restrict__ C, int ldc,
    int K, float alpha,
    int zdiv, long sA1, long sA2, long sB1, long sB2, long sC1, long sC2,
    int kz, long sAk, long sBk, long sCk)
{
    int z = blockIdx.z;
    int zc = z % kz; z /= kz;
    int z1 = z / zdiv, z2 = z % zdiv;
    A += z1 * sA1 + z2 * sA2 + zc * sAk;
    B += z1 * sB1 + z2 * sB2 + zc * sBk;
    C += z1 * sC1 + z2 * sC2 + zc * sCk;

    __shared__ float As[16][65];
    __shared__ float Bs[16][65];

    const int tid = threadIdx.x;
    const int tx = tid & 15;
    const int ty = tid >> 4;
    const int row0 = blockIdx.y * 64;
    const int col0 = blockIdx.x * 64;

    float acc[4][4] = {};

    for (int k0 = 0; k0 < K; k0 += 16) {
#pragma unroll
        for (int i = 0; i < 4; i++) {
            int e = tid + i * 256;
            if (TA == 0) {
                int r = e >> 4, c = e & 15;
                As[c][r] = A[(long)(row0 + r) * lda + k0 + c];
            } else {
                int r = e & 63, c = e >> 6;
                As[c][r] = A[(long)(k0 + c) * lda + row0 + r];
            }
        }
#pragma unroll
        for (int i = 0; i < 4; i++) {
            int e = tid + i * 256;
            if (TB == 0) {
                int r = e >> 6, c = e & 63;
                Bs[r][c] = B[(long)(k0 + r) * ldb + col0 + c];
            } else {
                int r = e & 15, c = e >> 4;
                Bs[r][c] = B[(long)(col0 + c) * ldb + k0 + r];
            }
        }
        __syncthreads();
#pragma unroll
        for (int kk = 0; kk < 16; kk++) {
            float av[4], bv[4];
#pragma unroll
            for (int i = 0; i < 4; i++) av[i] = As[kk][ty * 4 + i];
#pragma unroll
            for (int j = 0; j < 4; j++) bv[j] = Bs[kk][tx * 4 + j];
#pragma unroll
            for (int i = 0; i < 4; i++)
#pragma unroll
                for (int j = 0; j < 4; j++)
                    acc[i][j] = fmaf(av[i], bv[j], acc[i][j]);
        }
        __syncthreads();
    }

#pragma unroll
    for (int i = 0; i < 4; i++) {
        int row = row0 + ty * 4 + i;
#pragma unroll
        for (int j = 0; j < 4; j++) {
            int col = col0 + tx * 4 + j;
            float v = acc[i][j] * alpha;
            if (EPI >= 1) v += bias[col];
            if (EPI == 2) v = gelu_tanh(v);
            C[(long)row * ldc + col] = v;
        }
    }
}

__global__ void kv_reduce_kernel(const float* __restrict__ part, float* __restrict__ kvb)
{
    int idx = blockIdx.x * 256 + threadIdx.x;
    float s = 0.f;
#pragma unroll
    for (int i = 0; i < KVSPLIT; i++) s += part[(long)i * KVSLICE + idx];
    kvb[idx] = s;
}

// ---------------- embedding + layernorm ----------------
__global__ void embed_ln_kernel(const int* __restrict__ ids,
                                const int* __restrict__ tts,
                                const int* __restrict__ poss,
                                const float* __restrict__ we,
                                const float* __restrict__ pe,
                                const float* __restrict__ te,
                                const float* __restrict__ g,
                                const float* __restrict__ b,
                                float* __restrict__ out)
{
    int t = blockIdx.x;
    int id = ids[t], tk = tts[t], ps = poss[t];
    __shared__ float buf[HH];
    __shared__ float red[16];
    float s = 0.f, sq = 0.f;
    for (int h = threadIdx.x; h < HH; h += 256) {
        float v = we[(long)id * HH + h] + pe[(long)ps * HH + h] + te[(long)tk * HH + h];
        buf[h] = v; s += v; sq += v * v;
    }
    s = warp_sum(s); sq = warp_sum(sq);
    if ((threadIdx.x & 31) == 0) { red[threadIdx.x >> 5] = s; red[8 + (threadIdx.x >> 5)] = sq; }
    __syncthreads();
    float ts = 0.f, tq = 0.f;
#pragma unroll
    for (int i = 0; i < 8; i++) { ts += red[i]; tq += red[8 + i]; }
    float mu = ts * (1.f / HH);
    float var = tq * (1.f / HH) - mu * mu;
    float inv = rsqrtf(var + EPSF);
    for (int h = threadIdx.x; h < HH; h += 256)
        out[(long)t * HH + h] = (buf[h] - mu) * inv * g[h] + b[h];
}

// ---------------- residual + layernorm: out = LN(in1 + in2) ----------------
__global__ void ln_res_kernel(const float* __restrict__ in1,
                              const float* __restrict__ in2,
                              const float* __restrict__ g,
                              const float* __restrict__ b,
                              float* __restrict__ out)
{
    int t = blockIdx.x;
    __shared__ float buf[HH];
    __shared__ float red[16];
    float s = 0.f, sq = 0.f;
    for (int h = threadIdx.x; h < HH; h += 256) {
        float v = in1[(long)t * HH + h] + in2[(long)t * HH + h];
        buf[h] = v; s += v; sq += v * v;
    }
    s = warp_sum(s); sq = warp_sum(sq);
    if ((threadIdx.x & 31) == 0) { red[threadIdx.x >> 5] = s; red[8 + (threadIdx.x >> 5)] = sq; }
    __syncthreads();
    float ts = 0.f, tq = 0.f;
#pragma unroll
    for (int i = 0; i < 8; i++) { ts += red[i]; tq += red[8 + i]; }
    float mu = ts * (1.f / HH);
    float var = tq * (1.f / HH) - mu * mu;
    float inv = rsqrtf(var + EPSF);
    for (int h = threadIdx.x; h < HH; h += 256)
        out[(long)t * HH + h] = (buf[h] - mu) * inv * g[h] + b[h];
}

// ---------------- FAVOR+ epilogues ----------------
__global__ void q_epi_kernel(float* __restrict__ qp, const float* __restrict__ q)
{
    int row = blockIdx.x * 8 + (threadIdx.x >> 5);
    int lane = threadIdx.x & 31;
    const float* qr = q + (long)row * HDIM;
    float s = 0.f;
#pragma unroll
    for (int i = 0; i < 2; i++) { float v = qr[lane + i * 32] * DN; s += v * v; }
    s = warp_sum(s);
    float qd = 0.5f * s;
    float* qpr = qp + (long)row * MFEAT;
    float vals[8]; float mx = -INFINITY;
#pragma unroll
    for (int i = 0; i < 8; i++) { vals[i] = qpr[lane + i * 32]; mx = fmaxf(mx, vals[i]); }
    mx = warp_max(mx);
#pragma unroll
    for (int i = 0; i < 8; i++)
        qpr[lane + i * 32] = RATIO * (expf(vals[i] - qd - mx) + EPSF);
}

__global__ void kmax_init_kernel(float* __restrict__ kmax)
{
    if (threadIdx.x < BB * NHEAD) kmax[threadIdx.x] = -INFINITY;
}

__global__ void k_epi1_kernel(const float* __restrict__ kp, const float* __restrict__ k,
                              float* __restrict__ kd, float* __restrict__ kmax)
{
    int row = blockIdx.x * 8 + (threadIdx.x >> 5);
    int lane = threadIdx.x & 31;
    const float* kr = k + (long)row * HDIM;
    float s = 0.f;
#pragma unroll
    for (int i = 0; i < 2; i++) { float v = kr[lane + i * 32] * DN; s += v * v; }
    s = warp_sum(s);
    const float* kpr = kp + (long)row * MFEAT;
    float mx = -INFINITY;
#pragma unroll
    for (int i = 0; i < 8; i++) mx = fmaxf(mx, kpr[lane + i * 32]);
    mx = warp_max(mx);
    if (lane == 0) {
        kd[row] = 0.5f * s;
        int n = row % NHEAD;
        int t = row / NHEAD;
        int b = t >> 11;
        atomicMaxFloat(&kmax[b * NHEAD + n], mx);
    }
}

__global__ void k_epi2_kernel(float* __restrict__ kp, const float* __restrict__ kd,
                              const float* __restrict__ kmax, const int* __restrict__ am)
{
    long idx = (long)blockIdx.x * 256 + threadIdx.x;
    if (idx >= (long)NTOK * NHEAD * MFEAT) return;
    int row = (int)(idx >> 8);
    int n = row % NHEAD;
    int t = row / NHEAD;
    int b = t >> 11;
    float v = kp[idx];
    float r = RATIO * (expf(v - kd[row] - kmax[b * NHEAD + n]) + EPSF);
    kp[idx] = r * (float)am[t];
}

// ksum partials: grid (chunk=16, bn=24), each block sums 128 s-rows
__global__ void ksum_part_kernel(const float* __restrict__ kp, float* __restrict__ part)
{
    int chunk = blockIdx.x;
    int bn = blockIdx.y;
    int b = bn / NHEAD, n = bn % NHEAD;
    int m = threadIdx.x;
    const float* base = kp + ((long)(b * SS + chunk * 128) * NHEAD + n) * MFEAT + m;
    float s = 0.f;
    for (int i = 0; i < 128; i++) s += base[(long)i * NHEAD * MFEAT];
    part[(bn * 16 + chunk) * MFEAT + m] = s;
}

__global__ void ksum_reduce_kernel(const float* __restrict__ part, float* __restrict__ ksum)
{
    int bn = blockIdx.x;
    int m = threadIdx.x;
    float s = 0.f;
#pragma unroll
    for (int i = 0; i < 16; i++) s += part[(bn * 16 + i) * MFEAT + m];
    ksum[bn * MFEAT + m] = s;
}

__global__ void den_kernel(const float* __restrict__ qp, const float* __restrict__ ksum,
                           float* __restrict__ den)
{
    int row = blockIdx.x * 8 + (threadIdx.x >> 5);
    int lane = threadIdx.x & 31;
    int n = row % NHEAD;
    int t = row / NHEAD;
    int b = t >> 11;
    const float* qpr = qp + (long)row * MFEAT;
    const float* ks = ksum + (b * NHEAD + n) * MFEAT;
    float s = 0.f;
#pragma unroll
    for (int i = 0; i < 8; i++) { int m = lane + i * 32; s += qpr[m] * ks[m]; }
    s = warp_sum(s);
    if (lane == 0) den[row] = s;
}

__global__ void div_kernel(float* __restrict__ num, const float* __restrict__ den)
{
    long idx = (long)blockIdx.x * 256 + threadIdx.x;
    if (idx >= (long)NTOK * HH) return;
    num[idx] /= den[idx >> 6];
}

// ---------------- host launch ----------------
extern "C" void kernel_launch(void* const* d_in, const int* in_sizes, int n_in,
                              void* d_out, int out_size)
{
    const int* ids  = (const int*)d_in[0];
    const int* tts  = (const int*)d_in[1];
    const int* poss = (const int*)d_in[2];
    const int* am   = (const int*)d_in[3];
    const float* we   = (const float*)d_in[4];
    const float* pe   = (const float*)d_in[5];
    const float* te   = (const float*)d_in[6];
    const float* elg  = (const float*)d_in[7];
    const float* elb  = (const float*)d_in[8];
    const float* wq   = (const float*)d_in[9];
    const float* bq   = (const float*)d_in[10];
    const float* wk   = (const float*)d_in[11];
    const float* bk   = (const float*)d_in[12];
    const float* wv   = (const float*)d_in[13];
    const float* bv   = (const float*)d_in[14];
    const float* wo   = (const float*)d_in[15];
    const float* bo   = (const float*)d_in[16];
    const float* ln1g = (const float*)d_in[17];
    const float* ln1b = (const float*)d_in[18];
    const float* wi   = (const float*)d_in[19];
    const float* bi   = (const float*)d_in[20];
    const float* wo2  = (const float*)d_in[21];
    const float* bo2  = (const float*)d_in[22];
    const float* ln2g = (const float*)d_in[23];
    const float* ln2b = (const float*)d_in[24];
    const float* proj = (const float*)d_in[25];

    float *x, *a, *q, *k, *v, *qp, *kp, *kd, *kmax, *kvb, *kvpart, *ksum, *kspart,
          *num, *den, *attout, *inter, *ffout;
    cudaGetSymbolAddress((void**)&x, g_x);
    cudaGetSymbolAddress((void**)&a, g_a);
    cudaGetSymbolAddress((void**)&q, g_q);
    cudaGetSymbolAddress((void**)&k, g_k);
    cudaGetSymbolAddress((void**)&v, g_v);
    cudaGetSymbolAddress((void**)&qp, g_qp);
    cudaGetSymbolAddress((void**)&kp, g_kp);
    cudaGetSymbolAddress((void**)&kd, g_kd);
    cudaGetSymbolAddress((void**)&kmax, g_kmax);
    cudaGetSymbolAddress((void**)&kvb, g_kvb);
    cudaGetSymbolAddress((void**)&kvpart, g_kvpart);
    cudaGetSymbolAddress((void**)&ksum, g_ksum);
    cudaGetSymbolAddress((void**)&kspart, g_kspart);
    cudaGetSymbolAddress((void**)&num, g_num);
    cudaGetSymbolAddress((void**)&den, g_den);
    cudaGetSymbolAddress((void**)&attout, g_attout);
    cudaGetSymbolAddress((void**)&inter, g_inter);
    cudaGetSymbolAddress((void**)&ffout, g_ffout);

    embed_ln_kernel<<<NTOK, 256>>>(ids, tts, poss, we, pe, te, elg, elb, x);

    const long HW = (long)HH * HH;
    for (int l = 0; l < NLAYER; l++) {
        // ---- QKV projections (128x128 tiles) ----
        sgemm128_kernel<0, 1><<<dim3(HH / 128, NTOK / 128), 256>>>(
            x, HH, wq + l * HW, HH, bq + l * HH, q, HH, HH, 1.f);
        sgemm128_kernel<0, 1><<<dim3(HH / 128, NTOK / 128), 256>>>(
            x, HH, wk + l * HW, HH, bk + l * HH, k, HH, HH, 1.f);
        sgemm128_kernel<0, 1><<<dim3(HH / 128, NTOK / 128), 256>>>(
            x, HH, wv + l * HW, HH, bv + l * HH, v, HH, HH, 1.f);

        // ---- feature maps: qp = dn * q @ proj^T ----
        sgemm128_kernel<1, 0><<<dim3(MFEAT / 128, (NTOK * NHEAD) / 128), 256>>>(
            q, HDIM, proj + (long)l * MFEAT * HDIM, HDIM, nullptr, qp, MFEAT, HDIM, DN);
        sgemm128_kernel<1, 0><<<dim3(MFEAT / 128, (NTOK * NHEAD) / 128), 256>>>(
            k, HDIM, proj + (long)l * MFEAT * HDIM, HDIM, nullptr, kp, MFEAT, HDIM, DN);

        // ---- FAVOR epilogues ----
        q_epi_kernel<<<(NTOK * NHEAD) / 8, 256>>>(qp, q);
        kmax_init_kernel<<<1, 32>>>(kmax);
        k_epi1_kernel<<<(NTOK * NHEAD) / 8, 256>>>(kp, k, kd, kmax);
        {
            long total = (long)NTOK * NHEAD * MFEAT;
            k_epi2_kernel<<<(int)((total + 255) / 256), 256>>>(kp, kd, kmax, am);
        }

        // ---- kv = k'^T v, split-K x8, batched over 24 (b,n) ----
        sgemm_kernel<1, 0, 0><<<dim3(1, MFEAT / 64, BB * NHEAD * KVSPLIT), 256>>>(
            kp, NHEAD * MFEAT, v, HH, nullptr, kvpart, HDIM, SS / KVSPLIT, 1.f,
            NHEAD,
            (long)SS * NHEAD * MFEAT, MFEAT,
            (long)SS * HH, HDIM,
            (long)NHEAD * MFEAT * HDIM, (long)MFEAT * HDIM,
            KVSPLIT,
            (long)(SS / KVSPLIT) * NHEAD * MFEAT,
            (long)(SS / KVSPLIT) * HH,
            (long)KVSLICE);
        kv_reduce_kernel<<<KVSLICE / 256, 256>>>(kvpart, kvb);

        ksum_part_kernel<<<dim3(16, BB * NHEAD), MFEAT>>>(kp, kspart);
        ksum_reduce_kernel<<<BB * NHEAD, MFEAT>>>(kspart, ksum);

        // ---- num = q' @ kv, batched over 24 ----
        sgemm_kernel<0, 0, 0><<<dim3(1, SS / 64, BB * NHEAD), 256>>>(
            qp, NHEAD * MFEAT, kvb, HDIM, nullptr, num, HH, MFEAT, 1.f,
            NHEAD,
            (long)SS * NHEAD * MFEAT, MFEAT,
            (long)NHEAD * MFEAT * HDIM, (long)MFEAT * HDIM,
            (long)SS * HH, HDIM,
            1, 0, 0, 0);

        den_kernel<<<(NTOK * NHEAD) / 8, 256>>>(qp, ksum, den);
        {
            long total = (long)NTOK * HH;
            div_kernel<<<(int)((total + 255) / 256), 256>>>(num, den);
        }

        // ---- output projection + residual LN ----
        sgemm128_kernel<0, 1><<<dim3(HH / 128, NTOK / 128), 256>>>(
            num, HH, wo + l * HW, HH, bo + l * HH, attout, HH, HH, 1.f);
        ln_res_kernel<<<NTOK, 256>>>(attout, x, ln1g + l * HH, ln1b + l * HH, a);

        // ---- FFN ----
        sgemm128_kernel<0, 2><<<dim3(IFF / 128, NTOK / 128), 256>>>(
            a, HH, wi + (long)l * HH * IFF, IFF, bi + l * IFF, inter, IFF, HH, 1.f);
        sgemm128_kernel<0, 1><<<dim3(HH / 128, NTOK / 128), 256>>>(
            inter, IFF, wo2 + (long)l * IFF * HH, HH, bo2 + l * HH, ffout, HH, IFF, 1.f);

        float* outp = (l == NLAYER - 1) ? (float*)d_out : x;
        ln_res_kernel<<<NTOK, 256>>>(ffout, a, ln2g + l * HH, ln2b + l * HH, outp);
    }
}

// round 11
// speedup vs baseline: 1.9686x; 1.5127x over previous
#include <cuda_runtime.h>
#include <cuda_bf16.h>
#include <math.h>
#include <stdint.h>

// Problem dims
#define BB 2
#define SS 2048
#define NTOK 4096        // BB*SS
#define HH 768
#define NHEAD 12
#define HDIM 64
#define NLAYER 6
#define IFF 3072
#define MFEAT 256
#define EPSF 1e-6f
#define DN 0.3535533905932738f   // 1/sqrt(sqrt(64))
#define RATIO 0.0625f            // 1/sqrt(256)
#define KVSPLIT 8
#define KVSLICE (BB * NHEAD * MFEAT * HDIM)   // 393216

// ---------------- scratch (device globals; allocation-free) ----------------
__device__ float g_x[NTOK * HH];
__device__ float g_a[NTOK * HH];
__device__ float g_q[NTOK * HH];
__device__ float g_k[NTOK * HH];
__device__ float g_v[NTOK * HH];
__device__ float g_qp[(long)NTOK * NHEAD * MFEAT];
__device__ float g_kp[(long)NTOK * NHEAD * MFEAT];
__device__ float g_kd[NTOK * NHEAD];
__device__ float g_kmax[BB * NHEAD];
__device__ float g_kvb[KVSLICE];
__device__ float g_kvpart[KVSPLIT * KVSLICE];
__device__ float g_ksum[BB * NHEAD * MFEAT];
__device__ float g_kspart[BB * NHEAD * 16 * MFEAT];
__device__ float g_num[NTOK * HH];
__device__ float g_den[NTOK * NHEAD];
__device__ float g_attout[NTOK * HH];
__device__ float g_inter[(long)NTOK * IFF];
__device__ float g_ffout[NTOK * HH];

// ---------------- generic helpers ----------------
__device__ __forceinline__ float warp_sum(float v) {
#pragma unroll
    for (int o = 16; o > 0; o >>= 1) v += __shfl_xor_sync(0xffffffffu, v, o);
    return v;
}
__device__ __forceinline__ float warp_max(float v) {
#pragma unroll
    for (int o = 16; o > 0; o >>= 1) v = fmaxf(v, __shfl_xor_sync(0xffffffffu, v, o));
    return v;
}
__device__ __forceinline__ void atomicMaxFloat(float* addr, float val) {
    if (val >= 0.f) atomicMax((int*)addr, __float_as_int(val));
    else            atomicMin((unsigned int*)addr, __float_as_uint(val));
}
__device__ __forceinline__ float gelu_tanh(float v) {
    float x3 = v * v * v;
    return 0.5f * v * (1.f + tanhf(0.7978845608028654f * (v + 0.044715f * x3)));
}
__device__ __forceinline__ uint32_t smem_u32(const void* p) {
    uint32_t a;
    asm("{ .reg .u64 t; cvta.to.shared.u64 t, %1; cvt.u32.u64 %0, t; }" : "=r"(a) : "l"(p));
    return a;
}

// ---- bf16 split helpers ----
__device__ __forceinline__ unsigned short bhi(float a) {
    return __bfloat16_as_ushort(__float2bfloat16_rn(a));
}
__device__ __forceinline__ float bres(float a) {
    return a - __bfloat162float(__float2bfloat16_rn(a));
}
__device__ __forceinline__ uint32_t pack2(float a, float b) {
    return (uint32_t)bhi(a) | ((uint32_t)bhi(b) << 16);
}

// store float4 (4 orig k) as hi uint2 + lo uint2 into a row of layout
// [hi 64B | lo 64B], full 8-way 16B XOR swizzle (bijective on the 128B row)
__device__ __forceinline__ void st_hl(char* dst, int r, int c, float4 v) {
    uint2 hv = { pack2(v.x, v.y), pack2(v.z, v.w) };
    uint2 lv = { pack2(bres(v.x), bres(v.y)), pack2(bres(v.z), bres(v.w)) };
    int swz = (r & 7) << 4;
    char* rowp = dst + r * 128;
    *(uint2*)(rowp + ((c * 8) ^ swz)) = hv;
    *(uint2*)(rowp + ((64 + c * 8) ^ swz)) = lv;
}

__device__ __forceinline__ void ldsm4(uint32_t* r, uint32_t addr) {
    asm volatile("ldmatrix.sync.aligned.m8n8.x4.shared.b16 {%0,%1,%2,%3}, [%4];"
                 : "=r"(r[0]), "=r"(r[1]), "=r"(r[2]), "=r"(r[3]) : "r"(addr));
}
__device__ __forceinline__ void ldsm2(uint32_t* r, uint32_t addr) {
    asm volatile("ldmatrix.sync.aligned.m8n8.x2.shared.b16 {%0,%1}, [%2];"
                 : "=r"(r[0]), "=r"(r[1]) : "r"(addr));
}
__device__ __forceinline__ void mma16816(float* c, const uint32_t* a, const uint32_t* b) {
    asm volatile(
        "mma.sync.aligned.m16n8k16.row.col.f32.bf16.bf16.f32 "
        "{%0,%1,%2,%3}, {%4,%5,%6,%7}, {%8,%9}, {%0,%1,%2,%3};"
        : "+f"(c[0]), "+f"(c[1]), "+f"(c[2]), "+f"(c[3])
        : "r"(a[0]), "r"(a[1]), "r"(a[2]), "r"(a[3]), "r"(b[0]), "r"(b[1]));
}

// ====== bf16x3 (hi/lo split, 3 MMAs) GEMM: 128x128 tile, BK=32 orig k ======
// C = epi(alpha * A @ B'); A row-major [M,K]; TB=0: B [K,N]; TB=1: B [N,K].
// Per k16: acc += Ah*Bh + Al*Bh + Ah*Bl  (residual lo*lo ~ 2^-18).
// Smem stage: A 128x128B (hi|lo) = 16KB, B 16KB; double buffered = 64KB.
template <int TB, int EPI>
__global__ void __launch_bounds__(256) bgemm_kernel(
    const float* __restrict__ A, int lda,
    const float* __restrict__ B, int ldb,
    const float* __restrict__ bias,
    float* __restrict__ C, int ldc,
    int K, float alpha)
{
    extern __shared__ __align__(128) char smem[];
    const int tid = threadIdx.x;
    const int lane = tid & 31;
    const int wid = tid >> 5;
    const int wm = wid & 1;         // warp m (0/1) -> 64 rows
    const int wn = wid >> 1;        // warp n (0..3) -> 32 cols
    const int row0 = blockIdx.y * 128;
    const int col0 = blockIdx.x * 128;
    const uint32_t sbase = smem_u32(smem);

    float acc[4][4][4] = {};

    const int nch = K >> 5;   // chunks of 32 original k
    float4 fA[4];
    float4 fB4[4];
    float fBs[16];

    // ---- ldg chunk 0 ----
#pragma unroll
    for (int i = 0; i < 4; i++) {
        int e = i * 256 + tid, r = e >> 3, c = e & 7;
        fA[i] = *(const float4*)(A + (long)(row0 + r) * lda + c * 4);
    }
    if (TB == 1) {
#pragma unroll
        for (int i = 0; i < 4; i++) {
            int e = i * 256 + tid, r = e >> 3, c = e & 7;
            fB4[i] = *(const float4*)(B + (long)(col0 + r) * ldb + c * 4);
        }
    } else {
#pragma unroll
        for (int i = 0; i < 16; i++) {
            int e = i * 256 + tid, n = e & 127, kk = e >> 7;
            fBs[i] = B[(long)kk * ldb + col0 + n];
        }
    }
    // ---- store chunk 0 to stage 0 ----
#pragma unroll
    for (int i = 0; i < 4; i++) {
        int e = i * 256 + tid, r = e >> 3, c = e & 7;
        st_hl(smem, r, c, fA[i]);
    }
    if (TB == 1) {
#pragma unroll
        for (int i = 0; i < 4; i++) {
            int e = i * 256 + tid, r = e >> 3, c = e & 7;
            st_hl(smem + 16384, r, c, fB4[i]);
        }
    } else {
#pragma unroll
        for (int i = 0; i < 16; i++) {
            int e = i * 256 + tid, n = e & 127, kk = e >> 7;
            int swz = (n & 7) << 4;
            char* rowp = smem + 16384 + n * 128;
            *(unsigned short*)(rowp + ((kk * 2) ^ swz)) = bhi(fBs[i]);
            *(unsigned short*)(rowp + ((64 + kk * 2) ^ swz)) = bhi(bres(fBs[i]));
        }
    }
    __syncthreads();

    for (int ch = 0; ch < nch; ch++) {
        const bool more = (ch + 1) < nch;
        const int k0n = (ch + 1) << 5;
        if (more) {
#pragma unroll
            for (int i = 0; i < 4; i++) {
                int e = i * 256 + tid, r = e >> 3, c = e & 7;
                fA[i] = *(const float4*)(A + (long)(row0 + r) * lda + k0n + c * 4);
            }
            if (TB == 1) {
#pragma unroll
                for (int i = 0; i < 4; i++) {
                    int e = i * 256 + tid, r = e >> 3, c = e & 7;
                    fB4[i] = *(const float4*)(B + (long)(col0 + r) * ldb + k0n + c * 4);
                }
            } else {
#pragma unroll
                for (int i = 0; i < 16; i++) {
                    int e = i * 256 + tid, n = e & 127, kk = e >> 7;
                    fBs[i] = B[(long)(k0n + kk) * ldb + col0 + n];
                }
            }
        }

        // ---- compute from stage ch&1 ----
        {
            const uint32_t sA = sbase + (ch & 1) * 32768;
            const uint32_t sB = sA + 16384;
#pragma unroll
            for (int ks = 0; ks < 2; ks++) {          // 2 x k16 per 32-k chunk
                uint32_t ah[4][4], al[4][4], bh[4][2], bl[4][2];
#pragma unroll
                for (int mt = 0; mt < 4; mt++) {
                    int row = wm * 64 + mt * 16 + (lane & 15);
                    int swz = (row & 7) << 4;
                    uint32_t base = sA + row * 128;
                    int off = ks * 32 + ((lane >> 4) << 4);
                    ldsm4(ah[mt], base + (off ^ swz));
                    ldsm4(al[mt], base + ((64 + off) ^ swz));
                }
#pragma unroll
                for (int nt = 0; nt < 4; nt++) {
                    int n = wn * 32 + nt * 8 + (lane & 7);
                    int swz = (n & 7) << 4;
                    uint32_t base = sB + n * 128;
                    int off = ks * 32 + (((lane >> 3) & 1) << 4);
                    ldsm2(bh[nt], base + (off ^ swz));
                    ldsm2(bl[nt], base + ((64 + off) ^ swz));
                }
#pragma unroll
                for (int mt = 0; mt < 4; mt++)
#pragma unroll
                    for (int nt = 0; nt < 4; nt++) {
                        mma16816(acc[mt][nt], ah[mt], bh[nt]);
                        mma16816(acc[mt][nt], al[mt], bh[nt]);
                        mma16816(acc[mt][nt], ah[mt], bl[nt]);
                    }
            }
        }

        if (more) {
            char* dst = smem + ((ch + 1) & 1) * 32768;
#pragma unroll
            for (int i = 0; i < 4; i++) {
                int e = i * 256 + tid, r = e >> 3, c = e & 7;
                st_hl(dst, r, c, fA[i]);
            }
            if (TB == 1) {
#pragma unroll
                for (int i = 0; i < 4; i++) {
                    int e = i * 256 + tid, r = e >> 3, c = e & 7;
                    st_hl(dst + 16384, r, c, fB4[i]);
                }
            } else {
#pragma unroll
                for (int i = 0; i < 16; i++) {
                    int e = i * 256 + tid, n = e & 127, kk = e >> 7;
                    int swz = (n & 7) << 4;
                    char* rowp = dst + 16384 + n * 128;
                    *(unsigned short*)(rowp + ((kk * 2) ^ swz)) = bhi(fBs[i]);
                    *(unsigned short*)(rowp + ((64 + kk * 2) ^ swz)) = bhi(bres(fBs[i]));
                }
            }
        }
        __syncthreads();
    }

    // ---- epilogue ----
    const int r0 = lane >> 2;
    const int c0 = (lane & 3) * 2;
#pragma unroll
    for (int mt = 0; mt < 4; mt++) {
#pragma unroll
        for (int nt = 0; nt < 4; nt++) {
            int col = col0 + wn * 32 + nt * 8 + c0;
            float bx = 0.f, by = 0.f;
            if (EPI >= 1) { bx = bias[col]; by = bias[col + 1]; }
#pragma unroll
            for (int h = 0; h < 2; h++) {
                int row = row0 + wm * 64 + mt * 16 + r0 + h * 8;
                float vx = acc[mt][nt][h * 2 + 0] * alpha;
                float vy = acc[mt][nt][h * 2 + 1] * alpha;
                if (EPI >= 1) { vx += bx; vy += by; }
                if (EPI == 2) { vx = gelu_tanh(vx); vy = gelu_tanh(vy); }
                float2 o = { vx, vy };
                *(float2*)&C[(long)row * ldc + col] = o;
            }
        }
    }
}

// ================= generic 64x64 tiled SGEMM (batched, optional K-split) ===
template <int TA, int TB, int EPI>
__global__ void __launch_bounds__(256) sgemm_kernel(
    const float* __restrict__ A, int lda,
    const float* __restrict__ B, int ldb,
    const float* __restrict__ bias,
    float* __restrict__ C, int ldc,
    int K, float alpha,
    int zdiv, long sA1, long sA2, long sB1, long sB2, long sC1, long sC2,
    int kz, long sAk, long sBk, long sCk)
{
    int z = blockIdx.z;
    int zc = z % kz; z /= kz;
    int z1 = z / zdiv, z2 = z % zdiv;
    A += z1 * sA1 + z2 * sA2 + zc * sAk;
    B += z1 * sB1 + z2 * sB2 + zc * sBk;
    C += z1 * sC1 + z2 * sC2 + zc * sCk;

    __shared__ float As[16][65];
    __shared__ float Bs[16][65];

    const int tid = threadIdx.x;
    const int tx = tid & 15;
    const int ty = tid >> 4;
    const int row0 = blockIdx.y * 64;
    const int col0 = blockIdx.x * 64;

    float acc[4][4] = {};

    for (int k0 = 0; k0 < K; k0 += 16) {
#pragma unroll
        for (int i = 0; i < 4; i++) {
            int e = tid + i * 256;
            if (TA == 0) {
                int r = e >> 4, c = e & 15;
                As[c][r] = A[(long)(row0 + r) * lda + k0 + c];
            } else {
                int r = e & 63, c = e >> 6;
                As[c][r] = A[(long)(k0 + c) * lda + row0 + r];
            }
        }
#pragma unroll
        for (int i = 0; i < 4; i++) {
            int e = tid + i * 256;
            if (TB == 0) {
                int r = e >> 6, c = e & 63;
                Bs[r][c] = B[(long)(k0 + r) * ldb + col0 + c];
            } else {
                int r = e & 15, c = e >> 4;
                Bs[r][c] = B[(long)(col0 + c) * ldb + k0 + r];
            }
        }
        __syncthreads();
#pragma unroll
        for (int kk = 0; kk < 16; kk++) {
            float av[4], bv[4];
#pragma unroll
            for (int i = 0; i < 4; i++) av[i] = As[kk][ty * 4 + i];
#pragma unroll
            for (int j = 0; j < 4; j++) bv[j] = Bs[kk][tx * 4 + j];
#pragma unroll
            for (int i = 0; i < 4; i++)
#pragma unroll
                for (int j = 0; j < 4; j++)
                    acc[i][j] = fmaf(av[i], bv[j], acc[i][j]);
        }
        __syncthreads();
    }

#pragma unroll
    for (int i = 0; i < 4; i++) {
        int row = row0 + ty * 4 + i;
#pragma unroll
        for (int j = 0; j < 4; j++) {
            int col = col0 + tx * 4 + j;
            float v = acc[i][j] * alpha;
            if (EPI >= 1) v += bias[col];
            if (EPI == 2) v = gelu_tanh(v);
            C[(long)row * ldc + col] = v;
        }
    }
}

__global__ void kv_reduce_kernel(const float* __restrict__ part, float* __restrict__ kvb)
{
    int idx = blockIdx.x * 256 + threadIdx.x;
    float s = 0.f;
#pragma unroll
    for (int i = 0; i < KVSPLIT; i++) s += part[(long)i * KVSLICE + idx];
    kvb[idx] = s;
}

// ---------------- embedding + layernorm ----------------
__global__ void embed_ln_kernel(const int* __restrict__ ids,
                                const int* __restrict__ tts,
                                const int* __restrict__ poss,
                                const float* __restrict__ we,
                                const float* __restrict__ pe,
                                const float* __restrict__ te,
                                const float* __restrict__ g,
                                const float* __restrict__ b,
                                float* __restrict__ out)
{
    int t = blockIdx.x;
    int id = ids[t], tk = tts[t], ps = poss[t];
    __shared__ float buf[HH];
    __shared__ float red[16];
    float s = 0.f, sq = 0.f;
    for (int h = threadIdx.x; h < HH; h += 256) {
        float v = we[(long)id * HH + h] + pe[(long)ps * HH + h] + te[(long)tk * HH + h];
        buf[h] = v; s += v; sq += v * v;
    }
    s = warp_sum(s); sq = warp_sum(sq);
    if ((threadIdx.x & 31) == 0) { red[threadIdx.x >> 5] = s; red[8 + (threadIdx.x >> 5)] = sq; }
    __syncthreads();
    float ts = 0.f, tq = 0.f;
#pragma unroll
    for (int i = 0; i < 8; i++) { ts += red[i]; tq += red[8 + i]; }
    float mu = ts * (1.f / HH);
    float var = tq * (1.f / HH) - mu * mu;
    float inv = rsqrtf(var + EPSF);
    for (int h = threadIdx.x; h < HH; h += 256)
        out[(long)t * HH + h] = (buf[h] - mu) * inv * g[h] + b[h];
}

// ---------------- residual + layernorm: out = LN(in1 + in2) ----------------
__global__ void ln_res_kernel(const float* __restrict__ in1,
                              const float* __restrict__ in2,
                              const float* __restrict__ g,
                              const float* __restrict__ b,
                              float* __restrict__ out)
{
    int t = blockIdx.x;
    __shared__ float buf[HH];
    __shared__ float red[16];
    float s = 0.f, sq = 0.f;
    for (int h = threadIdx.x; h < HH; h += 256) {
        float v = in1[(long)t * HH + h] + in2[(long)t * HH + h];
        buf[h] = v; s += v; sq += v * v;
    }
    s = warp_sum(s); sq = warp_sum(sq);
    if ((threadIdx.x & 31) == 0) { red[threadIdx.x >> 5] = s; red[8 + (threadIdx.x >> 5)] = sq; }
    __syncthreads();
    float ts = 0.f, tq = 0.f;
#pragma unroll
    for (int i = 0; i < 8; i++) { ts += red[i]; tq += red[8 + i]; }
    float mu = ts * (1.f / HH);
    float var = tq * (1.f / HH) - mu * mu;
    float inv = rsqrtf(var + EPSF);
    for (int h = threadIdx.x; h < HH; h += 256)
        out[(long)t * HH + h] = (buf[h] - mu) * inv * g[h] + b[h];
}

// ---------------- FAVOR+ epilogues ----------------
__global__ void q_epi_kernel(float* __restrict__ qp, const float* __restrict__ q)
{
    int row = blockIdx.x * 8 + (threadIdx.x >> 5);
    int lane = threadIdx.x & 31;
    const float* qr = q + (long)row * HDIM;
    float s = 0.f;
#pragma unroll
    for (int i = 0; i < 2; i++) { float v = qr[lane + i * 32] * DN; s += v * v; }
    s = warp_sum(s);
    float qd = 0.5f * s;
    float* qpr = qp + (long)row * MFEAT;
    float vals[8]; float mx = -INFINITY;
#pragma unroll
    for (int i = 0; i < 8; i++) { vals[i] = qpr[lane + i * 32]; mx = fmaxf(mx, vals[i]); }
    mx = warp_max(mx);
#pragma unroll
    for (int i = 0; i < 8; i++)
        qpr[lane + i * 32] = RATIO * (expf(vals[i] - qd - mx) + EPSF);
}

__global__ void kmax_init_kernel(float* __restrict__ kmax)
{
    if (threadIdx.x < BB * NHEAD) kmax[threadIdx.x] = -INFINITY;
}

__global__ void k_epi1_kernel(const float* __restrict__ kp, const float* __restrict__ k,
                              float* __restrict__ kd, float* __restrict__ kmax)
{
    int row = blockIdx.x * 8 + (threadIdx.x >> 5);
    int lane = threadIdx.x & 31;
    const float* kr = k + (long)row * HDIM;
    float s = 0.f;
#pragma unroll
    for (int i = 0; i < 2; i++) { float v = kr[lane + i * 32] * DN; s += v * v; }
    s = warp_sum(s);
    const float* kpr = kp + (long)row * MFEAT;
    float mx = -INFINITY;
#pragma unroll
    for (int i = 0; i < 8; i++) mx = fmaxf(mx, kpr[lane + i * 32]);
    mx = warp_max(mx);
    if (lane == 0) {
        kd[row] = 0.5f * s;
        int n = row % NHEAD;
        int t = row / NHEAD;
        int b = t >> 11;
        atomicMaxFloat(&kmax[b * NHEAD + n], mx);
    }
}

__global__ void k_epi2_kernel(float* __restrict__ kp, const float* __restrict__ kd,
                              const float* __restrict__ kmax, const int* __restrict__ am)
{
    long idx = (long)blockIdx.x * 256 + threadIdx.x;
    if (idx >= (long)NTOK * NHEAD * MFEAT) return;
    int row = (int)(idx >> 8);
    int n = row % NHEAD;
    int t = row / NHEAD;
    int b = t >> 11;
    float v = kp[idx];
    float r = RATIO * (expf(v - kd[row] - kmax[b * NHEAD + n]) + EPSF);
    kp[idx] = r * (float)am[t];
}

__global__ void ksum_part_kernel(const float* __restrict__ kp, float* __restrict__ part)
{
    int chunk = blockIdx.x;
    int bn = blockIdx.y;
    int b = bn / NHEAD, n = bn % NHEAD;
    int m = threadIdx.x;
    const float* base = kp + ((long)(b * SS + chunk * 128) * NHEAD + n) * MFEAT + m;
    float s = 0.f;
    for (int i = 0; i < 128; i++) s += base[(long)i * NHEAD * MFEAT];
    part[(bn * 16 + chunk) * MFEAT + m] = s;
}

__global__ void ksum_reduce_kernel(const float* __restrict__ part, float* __restrict__ ksum)
{
    int bn = blockIdx.x;
    int m = threadIdx.x;
    float s = 0.f;
#pragma unroll
    for (int i = 0; i < 16; i++) s += part[(bn * 16 + i) * MFEAT + m];
    ksum[bn * MFEAT + m] = s;
}

__global__ void den_kernel(const float* __restrict__ qp, const float* __restrict__ ksum,
                           float* __restrict__ den)
{
    int row = blockIdx.x * 8 + (threadIdx.x >> 5);
    int lane = threadIdx.x & 31;
    int n = row % NHEAD;
    int t = row / NHEAD;
    int b = t >> 11;
    const float* qpr = qp + (long)row * MFEAT;
    const float* ks = ksum + (b * NHEAD + n) * MFEAT;
    float s = 0.f;
#pragma unroll
    for (int i = 0; i < 8; i++) { int m = lane + i * 32; s += qpr[m] * ks[m]; }
    s = warp_sum(s);
    if (lane == 0) den[row] = s;
}

__global__ void div_kernel(float* __restrict__ num, const float* __restrict__ den)
{
    long idx = (long)blockIdx.x * 256 + threadIdx.x;
    if (idx >= (long)NTOK * HH) return;
    num[idx] /= den[idx >> 6];
}

// ---------------- host launch ----------------
#define BG_SMEM 65536

extern "C" void kernel_launch(void* const* d_in, const int* in_sizes, int n_in,
                              void* d_out, int out_size)
{
    const int* ids  = (const int*)d_in[0];
    const int* tts  = (const int*)d_in[1];
    const int* poss = (const int*)d_in[2];
    const int* am   = (const int*)d_in[3];
    const float* we   = (const float*)d_in[4];
    const float* pe   = (const float*)d_in[5];
    const float* te   = (const float*)d_in[6];
    const float* elg  = (const float*)d_in[7];
    const float* elb  = (const float*)d_in[8];
    const float* wq   = (const float*)d_in[9];
    const float* bq   = (const float*)d_in[10];
    const float* wk   = (const float*)d_in[11];
    const float* bk   = (const float*)d_in[12];
    const float* wv   = (const float*)d_in[13];
    const float* bv   = (const float*)d_in[14];
    const float* wo   = (const float*)d_in[15];
    const float* bo   = (const float*)d_in[16];
    const float* ln1g = (const float*)d_in[17];
    const float* ln1b = (const float*)d_in[18];
    const float* wi   = (const float*)d_in[19];
    const float* bi   = (const float*)d_in[20];
    const float* wo2  = (const float*)d_in[21];
    const float* bo2  = (const float*)d_in[22];
    const float* ln2g = (const float*)d_in[23];
    const float* ln2b = (const float*)d_in[24];
    const float* proj = (const float*)d_in[25];

    float *x, *a, *q, *k, *v, *qp, *kp, *kd, *kmax, *kvb, *kvpart, *ksum, *kspart,
          *num, *den, *attout, *inter, *ffout;
    cudaGetSymbolAddress((void**)&x, g_x);
    cudaGetSymbolAddress((void**)&a, g_a);
    cudaGetSymbolAddress((void**)&q, g_q);
    cudaGetSymbolAddress((void**)&k, g_k);
    cudaGetSymbolAddress((void**)&v, g_v);
    cudaGetSymbolAddress((void**)&qp, g_qp);
    cudaGetSymbolAddress((void**)&kp, g_kp);
    cudaGetSymbolAddress((void**)&kd, g_kd);
    cudaGetSymbolAddress((void**)&kmax, g_kmax);
    cudaGetSymbolAddress((void**)&kvb, g_kvb);
    cudaGetSymbolAddress((void**)&kvpart, g_kvpart);
    cudaGetSymbolAddress((void**)&ksum, g_ksum);
    cudaGetSymbolAddress((void**)&kspart, g_kspart);
    cudaGetSymbolAddress((void**)&num, g_num);
    cudaGetSymbolAddress((void**)&den, g_den);
    cudaGetSymbolAddress((void**)&attout, g_attout);
    cudaGetSymbolAddress((void**)&inter, g_inter);
    cudaGetSymbolAddress((void**)&ffout, g_ffout);

    cudaFuncSetAttribute(bgemm_kernel<0, 1>, cudaFuncAttributeMaxDynamicSharedMemorySize, BG_SMEM);
    cudaFuncSetAttribute(bgemm_kernel<0, 2>, cudaFuncAttributeMaxDynamicSharedMemorySize, BG_SMEM);
    cudaFuncSetAttribute(bgemm_kernel<1, 0>, cudaFuncAttributeMaxDynamicSharedMemorySize, BG_SMEM);

    embed_ln_kernel<<<NTOK, 256>>>(ids, tts, poss, we, pe, te, elg, elb, x);

    const long HW = (long)HH * HH;
    for (int l = 0; l < NLAYER; l++) {
        // ---- QKV projections (bf16x3 mma) ----
        bgemm_kernel<0, 1><<<dim3(HH / 128, NTOK / 128), 256, BG_SMEM>>>(
            x, HH, wq + l * HW, HH, bq + l * HH, q, HH, HH, 1.f);
        bgemm_kernel<0, 1><<<dim3(HH / 128, NTOK / 128), 256, BG_SMEM>>>(
            x, HH, wk + l * HW, HH, bk + l * HH, k, HH, HH, 1.f);
        bgemm_kernel<0, 1><<<dim3(HH / 128, NTOK / 128), 256, BG_SMEM>>>(
            x, HH, wv + l * HW, HH, bv + l * HH, v, HH, HH, 1.f);

        // ---- feature maps: qp = dn * q @ proj^T ----
        bgemm_kernel<1, 0><<<dim3(MFEAT / 128, (NTOK * NHEAD) / 128), 256, BG_SMEM>>>(
            q, HDIM, proj + (long)l * MFEAT * HDIM, HDIM, nullptr, qp, MFEAT, HDIM, DN);
        bgemm_kernel<1, 0><<<dim3(MFEAT / 128, (NTOK * NHEAD) / 128), 256, BG_SMEM>>>(
            k, HDIM, proj + (long)l * MFEAT * HDIM, HDIM, nullptr, kp, MFEAT, HDIM, DN);

        // ---- FAVOR epilogues ----
        q_epi_kernel<<<(NTOK * NHEAD) / 8, 256>>>(qp, q);
        kmax_init_kernel<<<1, 32>>>(kmax);
        k_epi1_kernel<<<(NTOK * NHEAD) / 8, 256>>>(kp, k, kd, kmax);
        {
            long total = (long)NTOK * NHEAD * MFEAT;
            k_epi2_kernel<<<(int)((total + 255) / 256), 256>>>(kp, kd, kmax, am);
        }

        // ---- kv = k'^T v, split-K x8, batched over 24 (b,n) ----
        sgemm_kernel<1, 0, 0><<<dim3(1, MFEAT / 64, BB * NHEAD * KVSPLIT), 256>>>(
            kp, NHEAD * MFEAT, v, HH, nullptr, kvpart, HDIM, SS / KVSPLIT, 1.f,
            NHEAD,
            (long)SS * NHEAD * MFEAT, MFEAT,
            (long)SS * HH, HDIM,
            (long)NHEAD * MFEAT * HDIM, (long)MFEAT * HDIM,
            KVSPLIT,
            (long)(SS / KVSPLIT) * NHEAD * MFEAT,
            (long)(SS / KVSPLIT) * HH,
            (long)KVSLICE);
        kv_reduce_kernel<<<KVSLICE / 256, 256>>>(kvpart, kvb);

        ksum_part_kernel<<<dim3(16, BB * NHEAD), MFEAT>>>(kp, kspart);
        ksum_reduce_kernel<<<BB * NHEAD, MFEAT>>>(kspart, ksum);

        // ---- num = q' @ kv, batched over 24 ----
        sgemm_kernel<0, 0, 0><<<dim3(1, SS / 64, BB * NHEAD), 256>>>(
            qp, NHEAD * MFEAT, kvb, HDIM, nullptr, num, HH, MFEAT, 1.f,
            NHEAD,
            (long)SS * NHEAD * MFEAT, MFEAT,
            (long)NHEAD * MFEAT * HDIM, (long)MFEAT * HDIM,
            (long)SS * HH, HDIM,
            1, 0, 0, 0);

        den_kernel<<<(NTOK * NHEAD) / 8, 256>>>(qp, ksum, den);
        {
            long total = (long)NTOK * HH;
            div_kernel<<<(int)((total + 255) / 256), 256>>>(num, den);
        }

        // ---- output projection + residual LN ----
        bgemm_kernel<0, 1><<<dim3(HH / 128, NTOK / 128), 256, BG_SMEM>>>(
            num, HH, wo + l * HW, HH, bo + l * HH, attout, HH, HH, 1.f);
        ln_res_kernel<<<NTOK, 256>>>(attout, x, ln1g + l * HH, ln1b + l * HH, a);

        // ---- FFN ----
        bgemm_kernel<0, 2><<<dim3(IFF / 128, NTOK / 128), 256, BG_SMEM>>>(
            a, HH, wi + (long)l * HH * IFF, IFF, bi + l * IFF, inter, IFF, HH, 1.f);
        bgemm_kernel<0, 1><<<dim3(HH / 128, NTOK / 128), 256, BG_SMEM>>>(
            inter, IFF, wo2 + (long)l * IFF * HH, HH, bo2 + l * HH, ffout, HH, IFF, 1.f);

        float* outp = (l == NLAYER - 1) ? (float*)d_out : x;
        ln_res_kernel<<<NTOK, 256>>>(ffout, a, ln2g + l * HH, ln2b + l * HH, outp);
    }
}

// round 12
// speedup vs baseline: 2.3666x; 1.2022x over previous
#include <cuda_runtime.h>
#include <cuda_bf16.h>
#include <math.h>
#include <stdint.h>

// Problem dims
#define BB 2
#define SS 2048
#define NTOK 4096        // BB*SS
#define HH 768
#define NHEAD 12
#define HDIM 64
#define NLAYER 6
#define IFF 3072
#define MFEAT 256
#define EPSF 1e-6f
#define DN 0.3535533905932738f   // 1/sqrt(sqrt(64))
#define RATIO 0.0625f            // 1/sqrt(256)
#define KVSPLIT 8
#define KVSLICE (BB * NHEAD * MFEAT * HDIM)   // 393216

// ---------------- scratch (device globals; allocation-free) ----------------
__device__ float g_x[NTOK * HH];
__device__ float g_a[NTOK * HH];
__device__ float g_q[NTOK * HH];
__device__ float g_k[NTOK * HH];
__device__ float g_v[NTOK * HH];
__device__ float g_qp[(long)NTOK * NHEAD * MFEAT];
__device__ float g_kp[(long)NTOK * NHEAD * MFEAT];
__device__ float g_kd[NTOK * NHEAD];
__device__ float g_kmax[BB * NHEAD];
__device__ float g_kvb[KVSLICE];
__device__ float g_kvpart[KVSPLIT * KVSLICE];
__device__ float g_ksum[BB * NHEAD * MFEAT];
__device__ float g_kspart[BB * NHEAD * 16 * MFEAT];
__device__ float g_num[NTOK * HH];
__device__ float g_den[NTOK * NHEAD];
__device__ float g_attout[NTOK * HH];
__device__ float g_inter[(long)NTOK * IFF];
__device__ float g_ffout[NTOK * HH];

// ---------------- generic helpers ----------------
__device__ __forceinline__ float warp_sum(float v) {
#pragma unroll
    for (int o = 16; o > 0; o >>= 1) v += __shfl_xor_sync(0xffffffffu, v, o);
    return v;
}
__device__ __forceinline__ float warp_max(float v) {
#pragma unroll
    for (int o = 16; o > 0; o >>= 1) v = fmaxf(v, __shfl_xor_sync(0xffffffffu, v, o));
    return v;
}
__device__ __forceinline__ void atomicMaxFloat(float* addr, float val) {
    if (val >= 0.f) atomicMax((int*)addr, __float_as_int(val));
    else            atomicMin((unsigned int*)addr, __float_as_uint(val));
}
__device__ __forceinline__ float gelu_tanh(float v) {
    float x3 = v * v * v;
    return 0.5f * v * (1.f + tanhf(0.7978845608028654f * (v + 0.044715f * x3)));
}
__device__ __forceinline__ uint32_t smem_u32(const void* p) {
    uint32_t a;
    asm("{ .reg .u64 t; cvta.to.shared.u64 t, %1; cvt.u32.u64 %0, t; }" : "=r"(a) : "l"(p));
    return a;
}

// ---- bf16 split helpers ----
__device__ __forceinline__ unsigned short bhi(float a) {
    return __bfloat16_as_ushort(__float2bfloat16_rn(a));
}
__device__ __forceinline__ float bres(float a) {
    return a - __bfloat162float(__float2bfloat16_rn(a));
}
__device__ __forceinline__ uint32_t pack2(float a, float b) {
    return (uint32_t)bhi(a) | ((uint32_t)bhi(b) << 16);
}

// store float4 (4 orig k) as hi uint2 + lo uint2 into a row of layout
// [hi 64B | lo 64B], full 8-way 16B XOR swizzle (bijective on the 128B row)
__device__ __forceinline__ void st_hl(char* dst, int r, int c, float4 v) {
    uint2 hv = { pack2(v.x, v.y), pack2(v.z, v.w) };
    uint2 lv = { pack2(bres(v.x), bres(v.y)), pack2(bres(v.z), bres(v.w)) };
    int swz = (r & 7) << 4;
    char* rowp = dst + r * 128;
    *(uint2*)(rowp + ((c * 8) ^ swz)) = hv;
    *(uint2*)(rowp + ((64 + c * 8) ^ swz)) = lv;
}

__device__ __forceinline__ void ldsm4(uint32_t* r, uint32_t addr) {
    asm volatile("ldmatrix.sync.aligned.m8n8.x4.shared.b16 {%0,%1,%2,%3}, [%4];"
                 : "=r"(r[0]), "=r"(r[1]), "=r"(r[2]), "=r"(r[3]) : "r"(addr));
}
__device__ __forceinline__ void ldsm2(uint32_t* r, uint32_t addr) {
    asm volatile("ldmatrix.sync.aligned.m8n8.x2.shared.b16 {%0,%1}, [%2];"
                 : "=r"(r[0]), "=r"(r[1]) : "r"(addr));
}
__device__ __forceinline__ void mma16816(float* c, const uint32_t* a, const uint32_t* b) {
    asm volatile(
        "mma.sync.aligned.m16n8k16.row.col.f32.bf16.bf16.f32 "
        "{%0,%1,%2,%3}, {%4,%5,%6,%7}, {%8,%9}, {%0,%1,%2,%3};"
        : "+f"(c[0]), "+f"(c[1]), "+f"(c[2]), "+f"(c[3])
        : "r"(a[0]), "r"(a[1]), "r"(a[2]), "r"(a[3]), "r"(b[0]), "r"(b[1]));
}

// ====== bf16x3 (hi/lo split, 3 MMAs) GEMM: 128x64 tile, BK=32 orig k ======
// C = epi(alpha * A @ B'); A row-major [M,K]; TB=0: B [K,N]; TB=1: B [N,K].
// Per k16: acc += Ah*Bh + Al*Bh + Ah*Bl  (residual lo*lo ~ 2^-18).
// 8 warps: wm=wid&3 (32 rows), wn=wid>>2 (32 cols). Warp tile 32x32.
// Smem stage: A 128x128B (hi|lo)=16KB + B 64x128B=8KB; double buffered=48KB.
template <int TB, int EPI>
__global__ void __launch_bounds__(256, 2) bgemm_kernel(
    const float* __restrict__ A, int lda,
    const float* __restrict__ B, int ldb,
    const float* __restrict__ bias,
    float* __restrict__ C, int ldc,
    int K, float alpha)
{
    extern __shared__ __align__(128) char smem[];
    const int tid = threadIdx.x;
    const int lane = tid & 31;
    const int wid = tid >> 5;
    const int wm = wid & 3;         // warp m (0..3) -> 32 rows
    const int wn = wid >> 2;        // warp n (0..1) -> 32 cols
    const int row0 = blockIdx.y * 128;
    const int col0 = blockIdx.x * 64;
    const uint32_t sbase = smem_u32(smem);

    float acc[2][4][4] = {};

    const int nch = K >> 5;   // chunks of 32 original k
    float4 fA[4];
    float4 fB4[2];
    float fBs[8];

    // ---- ldg chunk 0 ----
#pragma unroll
    for (int i = 0; i < 4; i++) {
        int e = i * 256 + tid, r = e >> 3, c = e & 7;
        fA[i] = *(const float4*)(A + (long)(row0 + r) * lda + c * 4);
    }
    if (TB == 1) {
#pragma unroll
        for (int i = 0; i < 2; i++) {
            int e = i * 256 + tid, r = e >> 3, c = e & 7;
            fB4[i] = *(const float4*)(B + (long)(col0 + r) * ldb + c * 4);
        }
    } else {
#pragma unroll
        for (int i = 0; i < 8; i++) {
            int e = i * 256 + tid, n = e & 63, kk = e >> 6;
            fBs[i] = B[(long)kk * ldb + col0 + n];
        }
    }
    // ---- store chunk 0 to stage 0 ----
#pragma unroll
    for (int i = 0; i < 4; i++) {
        int e = i * 256 + tid, r = e >> 3, c = e & 7;
        st_hl(smem, r, c, fA[i]);
    }
    if (TB == 1) {
#pragma unroll
        for (int i = 0; i < 2; i++) {
            int e = i * 256 + tid, r = e >> 3, c = e & 7;
            st_hl(smem + 16384, r, c, fB4[i]);
        }
    } else {
#pragma unroll
        for (int i = 0; i < 8; i++) {
            int e = i * 256 + tid, n = e & 63, kk = e >> 6;
            int swz = (n & 7) << 4;
            char* rowp = smem + 16384 + n * 128;
            *(unsigned short*)(rowp + ((kk * 2) ^ swz)) = bhi(fBs[i]);
            *(unsigned short*)(rowp + ((64 + kk * 2) ^ swz)) = bhi(bres(fBs[i]));
        }
    }
    __syncthreads();

    for (int ch = 0; ch < nch; ch++) {
        const bool more = (ch + 1) < nch;
        const int k0n = (ch + 1) << 5;
        if (more) {
#pragma unroll
            for (int i = 0; i < 4; i++) {
                int e = i * 256 + tid, r = e >> 3, c = e & 7;
                fA[i] = *(const float4*)(A + (long)(row0 + r) * lda + k0n + c * 4);
            }
            if (TB == 1) {
#pragma unroll
                for (int i = 0; i < 2; i++) {
                    int e = i * 256 + tid, r = e >> 3, c = e & 7;
                    fB4[i] = *(const float4*)(B + (long)(col0 + r) * ldb + k0n + c * 4);
                }
            } else {
#pragma unroll
                for (int i = 0; i < 8; i++) {
                    int e = i * 256 + tid, n = e & 63, kk = e >> 6;
                    fBs[i] = B[(long)(k0n + kk) * ldb + col0 + n];
                }
            }
        }

        // ---- compute from stage ch&1 ----
        {
            const uint32_t sA = sbase + (ch & 1) * 24576;
            const uint32_t sB = sA + 16384;
#pragma unroll
            for (int ks = 0; ks < 2; ks++) {          // 2 x k16 per 32-k chunk
                uint32_t ah[2][4], al[2][4], bh[4][2], bl[4][2];
#pragma unroll
                for (int mt = 0; mt < 2; mt++) {
                    int row = wm * 32 + mt * 16 + (lane & 15);
                    int swz = (row & 7) << 4;
                    uint32_t base = sA + row * 128;
                    int off = ks * 32 + ((lane >> 4) << 4);
                    ldsm4(ah[mt], base + (off ^ swz));
                    ldsm4(al[mt], base + ((64 + off) ^ swz));
                }
#pragma unroll
                for (int nt = 0; nt < 4; nt++) {
                    int n = wn * 32 + nt * 8 + (lane & 7);
                    int swz = (n & 7) << 4;
                    uint32_t base = sB + n * 128;
                    int off = ks * 32 + (((lane >> 3) & 1) << 4);
                    ldsm2(bh[nt], base + (off ^ swz));
                    ldsm2(bl[nt], base + ((64 + off) ^ swz));
                }
#pragma unroll
                for (int mt = 0; mt < 2; mt++)
#pragma unroll
                    for (int nt = 0; nt < 4; nt++) {
                        mma16816(acc[mt][nt], ah[mt], bh[nt]);
                        mma16816(acc[mt][nt], al[mt], bh[nt]);
                        mma16816(acc[mt][nt], ah[mt], bl[nt]);
                    }
            }
        }

        if (more) {
            char* dst = smem + ((ch + 1) & 1) * 24576;
#pragma unroll
            for (int i = 0; i < 4; i++) {
                int e = i * 256 + tid, r = e >> 3, c = e & 7;
                st_hl(dst, r, c, fA[i]);
            }
            if (TB == 1) {
#pragma unroll
                for (int i = 0; i < 2; i++) {
                    int e = i * 256 + tid, r = e >> 3, c = e & 7;
                    st_hl(dst + 16384, r, c, fB4[i]);
                }
            } else {
#pragma unroll
                for (int i = 0; i < 8; i++) {
                    int e = i * 256 + tid, n = e & 63, kk = e >> 6;
                    int swz = (n & 7) << 4;
                    char* rowp = dst + 16384 + n * 128;
                    *(unsigned short*)(rowp + ((kk * 2) ^ swz)) = bhi(fBs[i]);
                    *(unsigned short*)(rowp + ((64 + kk * 2) ^ swz)) = bhi(bres(fBs[i]));
                }
            }
        }
        __syncthreads();
    }

    // ---- epilogue ----
    const int r0 = lane >> 2;
    const int c0 = (lane & 3) * 2;
#pragma unroll
    for (int mt = 0; mt < 2; mt++) {
#pragma unroll
        for (int nt = 0; nt < 4; nt++) {
            int col = col0 + wn * 32 + nt * 8 + c0;
            float bx = 0.f, by = 0.f;
            if (EPI >= 1) { bx = bias[col]; by = bias[col + 1]; }
#pragma unroll
            for (int h = 0; h < 2; h++) {
                int row = row0 + wm * 32 + mt * 16 + r0 + h * 8;
                float vx = acc[mt][nt][h * 2 + 0] * alpha;
                float vy = acc[mt][nt][h * 2 + 1] * alpha;
                if (EPI >= 1) { vx += bx; vy += by; }
                if (EPI == 2) { vx = gelu_tanh(vx); vy = gelu_tanh(vy); }
                float2 o = { vx, vy };
                *(float2*)&C[(long)row * ldc + col] = o;
            }
        }
    }
}

// ================= generic 64x64 tiled SGEMM (batched, optional K-split) ===
template <int TA, int TB, int EPI>
__global__ void __launch_bounds__(256) sgemm_kernel(
    const float* __restrict__ A, int lda,
    const float* __restrict__ B, int ldb,
    const float* __restrict__ bias,
    float* __restrict__ C, int ldc,
    int K, float alpha,
    int zdiv, long sA1, long sA2, long sB1, long sB2, long sC1, long sC2,
    int kz, long sAk, long sBk, long sCk)
{
    int z = blockIdx.z;
    int zc = z % kz; z /= kz;
    int z1 = z / zdiv, z2 = z % zdiv;
    A += z1 * sA1 + z2 * sA2 + zc * sAk;
    B += z1 * sB1 + z2 * sB2 + zc * sBk;
    C += z1 * sC1 + z2 * sC2 + zc * sCk;

    __shared__ float As[16][65];
    __shared__ float Bs[16][65];

    const int tid = threadIdx.x;
    const int tx = tid & 15;
    const int ty = tid >> 4;
    const int row0 = blockIdx.y * 64;
    const int col0 = blockIdx.x * 64;

    float acc[4][4] = {};

    for (int k0 = 0; k0 < K; k0 += 16) {
#pragma unroll
        for (int i = 0; i < 4; i++) {
            int e = tid + i * 256;
            if (TA == 0) {
                int r = e >> 4, c = e & 15;
                As[c][r] = A[(long)(row0 + r) * lda + k0 + c];
            } else {
                int r = e & 63, c = e >> 6;
                As[c][r] = A[(long)(k0 + c) * lda + row0 + r];
            }
        }
#pragma unroll
        for (int i = 0; i < 4; i++) {
            int e = tid + i * 256;
            if (TB == 0) {
                int r = e >> 6, c = e & 63;
                Bs[r][c] = B[(long)(k0 + r) * ldb + col0 + c];
            } else {
                int r = e & 15, c = e >> 4;
                Bs[r][c] = B[(long)(col0 + c) * ldb + k0 + r];
            }
        }
        __syncthreads();
#pragma unroll
        for (int kk = 0; kk < 16; kk++) {
            float av[4], bv[4];
#pragma unroll
            for (int i = 0; i < 4; i++) av[i] = As[kk][ty * 4 + i];
#pragma unroll
            for (int j = 0; j < 4; j++) bv[j] = Bs[kk][tx * 4 + j];
#pragma unroll
            for (int i = 0; i < 4; i++)
#pragma unroll
                for (int j = 0; j < 4; j++)
                    acc[i][j] = fmaf(av[i], bv[j], acc[i][j]);
        }
        __syncthreads();
    }

#pragma unroll
    for (int i = 0; i < 4; i++) {
        int row = row0 + ty * 4 + i;
#pragma unroll
        for (int j = 0; j < 4; j++) {
            int col = col0 + tx * 4 + j;
            float v = acc[i][j] * alpha;
            if (EPI >= 1) v += bias[col];
            if (EPI == 2) v = gelu_tanh(v);
            C[(long)row * ldc + col] = v;
        }
    }
}

__global__ void kv_reduce_kernel(const float* __restrict__ part, float* __restrict__ kvb)
{
    int idx = blockIdx.x * 256 + threadIdx.x;
    float s = 0.f;
#pragma unroll
    for (int i = 0; i < KVSPLIT; i++) s += part[(long)i * KVSLICE + idx];
    kvb[idx] = s;
}

// ---------------- embedding + layernorm ----------------
__global__ void embed_ln_kernel(const int* __restrict__ ids,
                                const int* __restrict__ tts,
                                const int* __restrict__ poss,
                                const float* __restrict__ we,
                                const float* __restrict__ pe,
                                const float* __restrict__ te,
                                const float* __restrict__ g,
                                const float* __restrict__ b,
                                float* __restrict__ out)
{
    int t = blockIdx.x;
    int id = ids[t], tk = tts[t], ps = poss[t];
    __shared__ float buf[HH];
    __shared__ float red[16];
    float s = 0.f, sq = 0.f;
    for (int h = threadIdx.x; h < HH; h += 256) {
        float v = we[(long)id * HH + h] + pe[(long)ps * HH + h] + te[(long)tk * HH + h];
        buf[h] = v; s += v; sq += v * v;
    }
    s = warp_sum(s); sq = warp_sum(sq);
    if ((threadIdx.x & 31) == 0) { red[threadIdx.x >> 5] = s; red[8 + (threadIdx.x >> 5)] = sq; }
    __syncthreads();
    float ts = 0.f, tq = 0.f;
#pragma unroll
    for (int i = 0; i < 8; i++) { ts += red[i]; tq += red[8 + i]; }
    float mu = ts * (1.f / HH);
    float var = tq * (1.f / HH) - mu * mu;
    float inv = rsqrtf(var + EPSF);
    for (int h = threadIdx.x; h < HH; h += 256)
        out[(long)t * HH + h] = (buf[h] - mu) * inv * g[h] + b[h];
}

// ---------------- residual + layernorm: out = LN(in1 + in2) ----------------
__global__ void ln_res_kernel(const float* __restrict__ in1,
                              const float* __restrict__ in2,
                              const float* __restrict__ g,
                              const float* __restrict__ b,
                              float* __restrict__ out)
{
    int t = blockIdx.x;
    __shared__ float buf[HH];
    __shared__ float red[16];
    float s = 0.f, sq = 0.f;
    for (int h = threadIdx.x; h < HH; h += 256) {
        float v = in1[(long)t * HH + h] + in2[(long)t * HH + h];
        buf[h] = v; s += v; sq += v * v;
    }
    s = warp_sum(s); sq = warp_sum(sq);
    if ((threadIdx.x & 31) == 0) { red[threadIdx.x >> 5] = s; red[8 + (threadIdx.x >> 5)] = sq; }
    __syncthreads();
    float ts = 0.f, tq = 0.f;
#pragma unroll
    for (int i = 0; i < 8; i++) { ts += red[i]; tq += red[8 + i]; }
    float mu = ts * (1.f / HH);
    float var = tq * (1.f / HH) - mu * mu;
    float inv = rsqrtf(var + EPSF);
    for (int h = threadIdx.x; h < HH; h += 256)
        out[(long)t * HH + h] = (buf[h] - mu) * inv * g[h] + b[h];
}

// ---------------- FAVOR+ epilogues ----------------
__global__ void q_epi_kernel(float* __restrict__ qp, const float* __restrict__ q)
{
    int row = blockIdx.x * 8 + (threadIdx.x >> 5);
    int lane = threadIdx.x & 31;
    const float* qr = q + (long)row * HDIM;
    float s = 0.f;
#pragma unroll
    for (int i = 0; i < 2; i++) { float v = qr[lane + i * 32] * DN; s += v * v; }
    s = warp_sum(s);
    float qd = 0.5f * s;
    float* qpr = qp + (long)row * MFEAT;
    float vals[8]; float mx = -INFINITY;
#pragma unroll
    for (int i = 0; i < 8; i++) { vals[i] = qpr[lane + i * 32]; mx = fmaxf(mx, vals[i]); }
    mx = warp_max(mx);
#pragma unroll
    for (int i = 0; i < 8; i++)
        qpr[lane + i * 32] = RATIO * (expf(vals[i] - qd - mx) + EPSF);
}

__global__ void kmax_init_kernel(float* __restrict__ kmax)
{
    if (threadIdx.x < BB * NHEAD) kmax[threadIdx.x] = -INFINITY;
}

__global__ void k_epi1_kernel(const float* __restrict__ kp, const float* __restrict__ k,
                              float* __restrict__ kd, float* __restrict__ kmax)
{
    int row = blockIdx.x * 8 + (threadIdx.x >> 5);
    int lane = threadIdx.x & 31;
    const float* kr = k + (long)row * HDIM;
    float s = 0.f;
#pragma unroll
    for (int i = 0; i < 2; i++) { float v = kr[lane + i * 32] * DN; s += v * v; }
    s = warp_sum(s);
    const float* kpr = kp + (long)row * MFEAT;
    float mx = -INFINITY;
#pragma unroll
    for (int i = 0; i < 8; i++) mx = fmaxf(mx, kpr[lane + i * 32]);
    mx = warp_max(mx);
    if (lane == 0) {
        kd[row] = 0.5f * s;
        int n = row % NHEAD;
        int t = row / NHEAD;
        int b = t >> 11;
        atomicMaxFloat(&kmax[b * NHEAD + n], mx);
    }
}

__global__ void k_epi2_kernel(float* __restrict__ kp, const float* __restrict__ kd,
                              const float* __restrict__ kmax, const int* __restrict__ am)
{
    long idx = (long)blockIdx.x * 256 + threadIdx.x;
    if (idx >= (long)NTOK * NHEAD * MFEAT) return;
    int row = (int)(idx >> 8);
    int n = row % NHEAD;
    int t = row / NHEAD;
    int b = t >> 11;
    float v = kp[idx];
    float r = RATIO * (expf(v - kd[row] - kmax[b * NHEAD + n]) + EPSF);
    kp[idx] = r * (float)am[t];
}

__global__ void ksum_part_kernel(const float* __restrict__ kp, float* __restrict__ part)
{
    int chunk = blockIdx.x;
    int bn = blockIdx.y;
    int b = bn / NHEAD, n = bn % NHEAD;
    int m = threadIdx.x;
    const float* base = kp + ((long)(b * SS + chunk * 128) * NHEAD + n) * MFEAT + m;
    float s = 0.f;
    for (int i = 0; i < 128; i++) s += base[(long)i * NHEAD * MFEAT];
    part[(bn * 16 + chunk) * MFEAT + m] = s;
}

__global__ void ksum_reduce_kernel(const float* __restrict__ part, float* __restrict__ ksum)
{
    int bn = blockIdx.x;
    int m = threadIdx.x;
    float s = 0.f;
#pragma unroll
    for (int i = 0; i < 16; i++) s += part[(bn * 16 + i) * MFEAT + m];
    ksum[bn * MFEAT + m] = s;
}

__global__ void den_kernel(const float* __restrict__ qp, const float* __restrict__ ksum,
                           float* __restrict__ den)
{
    int row = blockIdx.x * 8 + (threadIdx.x >> 5);
    int lane = threadIdx.x & 31;
    int n = row % NHEAD;
    int t = row / NHEAD;
    int b = t >> 11;
    const float* qpr = qp + (long)row * MFEAT;
    const float* ks = ksum + (b * NHEAD + n) * MFEAT;
    float s = 0.f;
#pragma unroll
    for (int i = 0; i < 8; i++) { int m = lane + i * 32; s += qpr[m] * ks[m]; }
    s = warp_sum(s);
    if (lane == 0) den[row] = s;
}

__global__ void div_kernel(float* __restrict__ num, const float* __restrict__ den)
{
    long idx = (long)blockIdx.x * 256 + threadIdx.x;
    if (idx >= (long)NTOK * HH) return;
    num[idx] /= den[idx >> 6];
}

// ---------------- host launch ----------------
#define BG_SMEM 49152

extern "C" void kernel_launch(void* const* d_in, const int* in_sizes, int n_in,
                              void* d_out, int out_size)
{
    const int* ids  = (const int*)d_in[0];
    const int* tts  = (const int*)d_in[1];
    const int* poss = (const int*)d_in[2];
    const int* am   = (const int*)d_in[3];
    const float* we   = (const float*)d_in[4];
    const float* pe   = (const float*)d_in[5];
    const float* te   = (const float*)d_in[6];
    const float* elg  = (const float*)d_in[7];
    const float* elb  = (const float*)d_in[8];
    const float* wq   = (const float*)d_in[9];
    const float* bq   = (const float*)d_in[10];
    const float* wk   = (const float*)d_in[11];
    const float* bk   = (const float*)d_in[12];
    const float* wv   = (const float*)d_in[13];
    const float* bv   = (const float*)d_in[14];
    const float* wo   = (const float*)d_in[15];
    const float* bo   = (const float*)d_in[16];
    const float* ln1g = (const float*)d_in[17];
    const float* ln1b = (const float*)d_in[18];
    const float* wi   = (const float*)d_in[19];
    const float* bi   = (const float*)d_in[20];
    const float* wo2  = (const float*)d_in[21];
    const float* bo2  = (const float*)d_in[22];
    const float* ln2g = (const float*)d_in[23];
    const float* ln2b = (const float*)d_in[24];
    const float* proj = (const float*)d_in[25];

    float *x, *a, *q, *k, *v, *qp, *kp, *kd, *kmax, *kvb, *kvpart, *ksum, *kspart,
          *num, *den, *attout, *inter, *ffout;
    cudaGetSymbolAddress((void**)&x, g_x);
    cudaGetSymbolAddress((void**)&a, g_a);
    cudaGetSymbolAddress((void**)&q, g_q);
    cudaGetSymbolAddress((void**)&k, g_k);
    cudaGetSymbolAddress((void**)&v, g_v);
    cudaGetSymbolAddress((void**)&qp, g_qp);
    cudaGetSymbolAddress((void**)&kp, g_kp);
    cudaGetSymbolAddress((void**)&kd, g_kd);
    cudaGetSymbolAddress((void**)&kmax, g_kmax);
    cudaGetSymbolAddress((void**)&kvb, g_kvb);
    cudaGetSymbolAddress((void**)&kvpart, g_kvpart);
    cudaGetSymbolAddress((void**)&ksum, g_ksum);
    cudaGetSymbolAddress((void**)&kspart, g_kspart);
    cudaGetSymbolAddress((void**)&num, g_num);
    cudaGetSymbolAddress((void**)&den, g_den);
    cudaGetSymbolAddress((void**)&attout, g_attout);
    cudaGetSymbolAddress((void**)&inter, g_inter);
    cudaGetSymbolAddress((void**)&ffout, g_ffout);

    cudaFuncSetAttribute(bgemm_kernel<0, 1>, cudaFuncAttributeMaxDynamicSharedMemorySize, BG_SMEM);
    cudaFuncSetAttribute(bgemm_kernel<0, 2>, cudaFuncAttributeMaxDynamicSharedMemorySize, BG_SMEM);
    cudaFuncSetAttribute(bgemm_kernel<1, 0>, cudaFuncAttributeMaxDynamicSharedMemorySize, BG_SMEM);

    embed_ln_kernel<<<NTOK, 256>>>(ids, tts, poss, we, pe, te, elg, elb, x);

    const long HW = (long)HH * HH;
    for (int l = 0; l < NLAYER; l++) {
        // ---- QKV projections (bf16x3 mma) ----
        bgemm_kernel<0, 1><<<dim3(HH / 64, NTOK / 128), 256, BG_SMEM>>>(
            x, HH, wq + l * HW, HH, bq + l * HH, q, HH, HH, 1.f);
        bgemm_kernel<0, 1><<<dim3(HH / 64, NTOK / 128), 256, BG_SMEM>>>(
            x, HH, wk + l * HW, HH, bk + l * HH, k, HH, HH, 1.f);
        bgemm_kernel<0, 1><<<dim3(HH / 64, NTOK / 128), 256, BG_SMEM>>>(
            x, HH, wv + l * HW, HH, bv + l * HH, v, HH, HH, 1.f);

        // ---- feature maps: qp = dn * q @ proj^T ----
        bgemm_kernel<1, 0><<<dim3(MFEAT / 64, (NTOK * NHEAD) / 128), 256, BG_SMEM>>>(
            q, HDIM, proj + (long)l * MFEAT * HDIM, HDIM, nullptr, qp, MFEAT, HDIM, DN);
        bgemm_kernel<1, 0><<<dim3(MFEAT / 64, (NTOK * NHEAD) / 128), 256, BG_SMEM>>>(
            k, HDIM, proj + (long)l * MFEAT * HDIM, HDIM, nullptr, kp, MFEAT, HDIM, DN);

        // ---- FAVOR epilogues ----
        q_epi_kernel<<<(NTOK * NHEAD) / 8, 256>>>(qp, q);
        kmax_init_kernel<<<1, 32>>>(kmax);
        k_epi1_kernel<<<(NTOK * NHEAD) / 8, 256>>>(kp, k, kd, kmax);
        {
            long total = (long)NTOK * NHEAD * MFEAT;
            k_epi2_kernel<<<(int)((total + 255) / 256), 256>>>(kp, kd, kmax, am);
        }

        // ---- kv = k'^T v, split-K x8, batched over 24 (b,n) ----
        sgemm_kernel<1, 0, 0><<<dim3(1, MFEAT / 64, BB * NHEAD * KVSPLIT), 256>>>(
            kp, NHEAD * MFEAT, v, HH, nullptr, kvpart, HDIM, SS / KVSPLIT, 1.f,
            NHEAD,
            (long)SS * NHEAD * MFEAT, MFEAT,
            (long)SS * HH, HDIM,
            (long)NHEAD * MFEAT * HDIM, (long)MFEAT * HDIM,
            KVSPLIT,
            (long)(SS / KVSPLIT) * NHEAD * MFEAT,
            (long)(SS / KVSPLIT) * HH,
            (long)KVSLICE);
        kv_reduce_kernel<<<KVSLICE / 256, 256>>>(kvpart, kvb);

        ksum_part_kernel<<<dim3(16, BB * NHEAD), MFEAT>>>(kp, kspart);
        ksum_reduce_kernel<<<BB * NHEAD, MFEAT>>>(kspart, ksum);

        // ---- num = q' @ kv, batched over 24 ----
        sgemm_kernel<0, 0, 0><<<dim3(1, SS / 64, BB * NHEAD), 256>>>(
            qp, NHEAD * MFEAT, kvb, HDIM, nullptr, num, HH, MFEAT, 1.f,
            NHEAD,
            (long)SS * NHEAD * MFEAT, MFEAT,
            (long)NHEAD * MFEAT * HDIM, (long)MFEAT * HDIM,
            (long)SS * HH, HDIM,
            1, 0, 0, 0);

        den_kernel<<<(NTOK * NHEAD) / 8, 256>>>(qp, ksum, den);
        {
            long total = (long)NTOK * HH;
            div_kernel<<<(int)((total + 255) / 256), 256>>>(num, den);
        }

        // ---- output projection + residual LN ----
        bgemm_kernel<0, 1><<<dim3(HH / 64, NTOK / 128), 256, BG_SMEM>>>(
            num, HH, wo + l * HW, HH, bo + l * HH, attout, HH, HH, 1.f);
        ln_res_kernel<<<NTOK, 256>>>(attout, x, ln1g + l * HH, ln1b + l * HH, a);

        // ---- FFN ----
        bgemm_kernel<0, 2><<<dim3(IFF / 64, NTOK / 128), 256, BG_SMEM>>>(
            a, HH, wi + (long)l * HH * IFF, IFF, bi + l * IFF, inter, IFF, HH, 1.f);
        bgemm_kernel<0, 1><<<dim3(HH / 64, NTOK / 128), 256, BG_SMEM>>>(
            inter, IFF, wo2 + (long)l * IFF * HH, HH, bo2 + l * HH, ffout, HH, IFF, 1.f);

        float* outp = (l == NLAYER - 1) ? (float*)d_out : x;
        ln_res_kernel<<<NTOK, 256>>>(ffout, a, ln2g + l * HH, ln2b + l * HH, outp);
    }
}